// round 5
// baseline (speedup 1.0000x reference)
#include <cuda_runtime.h>
#include <cstdint>

#define SEQ 2048
#define NB 2
#define ROWS (NB * SEQ)      // 4096 total (b,s) rows
#define HDIM 4096
#define NH 32
#define NKV 8
#define HD 128
#define QLD (NH * HD)        // 4096
#define KLD (NKV * HD)       // 1024
#define NBH (NB * NH)        // 64

// ---------------- scratch (static device allocations; no cudaMalloc) -------
__device__ float g_q[(size_t)ROWS * QLD];                 // 64 MB
__device__ float g_k[(size_t)ROWS * KLD];                 // 16 MB
__device__ float g_v[(size_t)ROWS * KLD];                 // 16 MB
__device__ float g_attn[(size_t)ROWS * QLD];              // 64 MB

// ---------------- helpers ---------------------------------------------------
__device__ __forceinline__ uint32_t smem_u32(const void* p) {
    uint32_t a;
    asm("{ .reg .u64 t; cvta.to.shared.u64 t, %1; cvt.u32.u64 %0, t; }" : "=r"(a) : "l"(p));
    return a;
}
__device__ __forceinline__ uint32_t f2tf(float f) {
    uint32_t u;
    asm("cvt.rna.tf32.f32 %0, %1;" : "=r"(u) : "f"(f));
    return u;
}
__device__ __forceinline__ float round_tf(float f) {
    return __uint_as_float(f2tf(f));
}

#define CP_ASYNC16(dst, src) \
    asm volatile("cp.async.cg.shared.global [%0], [%1], 16;" :: "r"(dst), "l"(src) : "memory")
#define CP_COMMIT() asm volatile("cp.async.commit_group;" ::: "memory")
#define CP_WAIT(n)  asm volatile("cp.async.wait_group %0;" :: "n"(n) : "memory")

__device__ __forceinline__ void mma8(float* c, const uint32_t* a, const uint32_t* b) {
    asm volatile(
        "mma.sync.aligned.m16n8k8.row.col.f32.tf32.tf32.f32 "
        "{%0,%1,%2,%3}, {%4,%5,%6,%7}, {%8,%9}, {%0,%1,%2,%3};\n"
        : "+f"(c[0]), "+f"(c[1]), "+f"(c[2]), "+f"(c[3])
        : "r"(a[0]), "r"(a[1]), "r"(a[2]), "r"(a[3]), "r"(b[0]), "r"(b[1]));
}

// ============================================================================
// Projection GEMM: C[256,128] tile = A * B^T, fp32 in (rounded to tf32 at
// fragment load), fp32 out.  A [M,K], B [N,K] row-major.
// 256 threads = 8 warps (4m x 2n), warp tile 64x64.  BK=16, 4-stage cp.async.
// ============================================================================
#define PBK 16
#define PSTAGE 4
#define PASTR 20
#define PBSTR 20
#define PA_BYTES (256 * PASTR * 4)          // 20480
#define PB_BYTES (128 * PBSTR * 4)          // 10240
#define PSTAGE_BYTES (PA_BYTES + PB_BYTES)  // 30720
#define PSMEM (PSTAGE * PSTAGE_BYTES)       // 122880

template <bool RND>
__device__ __forceinline__ void pgemm(
    const float* __restrict__ A, const float* __restrict__ B, float* __restrict__ C,
    int m0, int n0, int K, int lda, int ldb, int ldc)
{
    extern __shared__ float dsm[];
    const uint32_t sbase = smem_u32(dsm);

    const int tid = threadIdx.x;
    const int am = tid >> 2;            // 0..63
    const int ak = (tid & 3) << 2;      // 0,4,8,12

    const int warp = tid >> 5;
    const int lane = tid & 31;
    const int wm = (warp & 3) << 6;     // 0,64,128,192
    const int wn = (warp >> 2) << 6;    // 0,64
    const int g  = lane >> 2;
    const int tg = lane & 3;

    float acc[4][8][4];
#pragma unroll
    for (int i = 0; i < 4; i++)
#pragma unroll
        for (int j = 0; j < 8; j++)
#pragma unroll
            for (int l = 0; l < 4; l++) acc[i][j][l] = 0.f;

    const int nk = K / PBK;

#define PLOAD(s) do {                                                              \
        const uint32_t sa_u = sbase + ((s) & (PSTAGE - 1)) * PSTAGE_BYTES;         \
        const uint32_t sb_u = sa_u + PA_BYTES;                                     \
        const float* pa_ = A + (size_t)(m0 + am) * lda + (s) * PBK + ak;           \
        CP_ASYNC16(sa_u + (uint32_t)(am * PASTR + ak) * 4u, pa_);                  \
        CP_ASYNC16(sa_u + (uint32_t)((am + 64) * PASTR + ak) * 4u,                 \
                   pa_ + (size_t)64 * lda);                                        \
        CP_ASYNC16(sa_u + (uint32_t)((am + 128) * PASTR + ak) * 4u,                \
                   pa_ + (size_t)128 * lda);                                       \
        CP_ASYNC16(sa_u + (uint32_t)((am + 192) * PASTR + ak) * 4u,                \
                   pa_ + (size_t)192 * lda);                                       \
        const float* pb_ = B + (size_t)(n0 + am) * ldb + (s) * PBK + ak;           \
        CP_ASYNC16(sb_u + (uint32_t)(am * PBSTR + ak) * 4u, pb_);                  \
        CP_ASYNC16(sb_u + (uint32_t)((am + 64) * PBSTR + ak) * 4u,                 \
                   pb_ + (size_t)64 * ldb);                                        \
    } while (0)

#pragma unroll
    for (int s = 0; s < PSTAGE - 1; s++) {
        if (s < nk) PLOAD(s);
        CP_COMMIT();
    }

    for (int kt = 0; kt < nk; kt++) {
        CP_WAIT(PSTAGE - 2);
        __syncthreads();
        if (kt + PSTAGE - 1 < nk) PLOAD(kt + PSTAGE - 1);
        CP_COMMIT();

        const float* sa = dsm + (size_t)(kt & (PSTAGE - 1)) * (PSTAGE_BYTES / 4);
        const float* sb = sa + PA_BYTES / 4;

#pragma unroll
        for (int ks = 0; ks < 2; ks++) {
            const int kb = ks * 8;
            uint32_t af[4][4];
#pragma unroll
            for (int mt = 0; mt < 4; mt++) {
                const float* base = &sa[(wm + mt * 16 + g) * PASTR + kb + tg];
                af[mt][0] = f2tf(base[0]);
                af[mt][1] = f2tf(base[8 * PASTR]);
                af[mt][2] = f2tf(base[4]);
                af[mt][3] = f2tf(base[8 * PASTR + 4]);
            }
            uint32_t bf[8][2];
#pragma unroll
            for (int nt = 0; nt < 8; nt++) {
                const float* base = &sb[(wn + nt * 8 + g) * PBSTR + kb + tg];
                bf[nt][0] = f2tf(base[0]);
                bf[nt][1] = f2tf(base[4]);
            }
#pragma unroll
            for (int mt = 0; mt < 4; mt++)
#pragma unroll
                for (int nt = 0; nt < 8; nt++)
                    mma8(acc[mt][nt], af[mt], bf[nt]);
        }
        __syncthreads();
    }

#pragma unroll
    for (int mt = 0; mt < 4; mt++) {
        const int r = m0 + wm + mt * 16 + g;
#pragma unroll
        for (int nt = 0; nt < 8; nt++) {
            const int c = n0 + wn + nt * 8 + (tg << 1);
            float v0 = acc[mt][nt][0], v1 = acc[mt][nt][1];
            float v2 = acc[mt][nt][2], v3 = acc[mt][nt][3];
            if (RND) {
                v0 = round_tf(v0); v1 = round_tf(v1);
                v2 = round_tf(v2); v3 = round_tf(v3);
            }
            float* p0 = C + (size_t)r * ldc + c;
            *(float2*)p0 = make_float2(v0, v1);
            float* p1 = p0 + (size_t)8 * ldc;
            *(float2*)p1 = make_float2(v2, v3);
        }
    }
#undef PLOAD
}

// ---------------- projection wrappers ----------------------------------------
__global__ void __launch_bounds__(256, 1) k_proj_q(const float* __restrict__ hs,
                                                   const float* __restrict__ W) {
    pgemm<false>(hs, W, g_q, blockIdx.y * 256, blockIdx.x * 128, HDIM, HDIM, HDIM, QLD);
}
__global__ void __launch_bounds__(256, 1) k_proj_k(const float* __restrict__ hs,
                                                   const float* __restrict__ W) {
    pgemm<false>(hs, W, g_k, blockIdx.y * 256, blockIdx.x * 128, HDIM, HDIM, HDIM, KLD);
}
__global__ void __launch_bounds__(256, 1) k_proj_v(const float* __restrict__ hs,
                                                   const float* __restrict__ W) {
    pgemm<true>(hs, W, g_v, blockIdx.y * 256, blockIdx.x * 128, HDIM, HDIM, HDIM, KLD);
}
__global__ void __launch_bounds__(256, 1) k_out_proj(const float* __restrict__ W,
                                                     float* __restrict__ out) {
    pgemm<false>(g_attn, W, out, blockIdx.y * 256, blockIdx.x * 128, QLD, QLD, HDIM, HDIM);
}

// ============================================================================
// Fused flash attention (causal, online softmax).
// Grid (16 q-blocks [reversed], 64 z).  256 threads = 8 warps, 16 Q rows each.
// Q is pre-scaled by 1/sqrt(HD) in rope_q.
// ============================================================================
#define FKSTR 132
#define FVSTR 136
#define FK_U32 (64 * FKSTR)       // 8448
#define FV_U32 (64 * FVSTR)       // 8704
#define FSMEM ((2 * FK_U32 + 2 * FV_U32) * 4)   // 137216 bytes

__global__ void __launch_bounds__(256, 1) k_flash() {
    extern __shared__ uint32_t fsm[];
    const uint32_t sbase = smem_u32(fsm);

    const int tid = threadIdx.x;
    const int wid = tid >> 5, lane = tid & 31;
    const int g = lane >> 2, tg = lane & 3;
    const int wm = wid * 16;

    const int z = blockIdx.y, b = z >> 5, h = z & 31, kvh = h >> 2;
    const int qb = (int)(gridDim.x - 1 - blockIdx.x);
    const int q0 = qb * 128;
    const int nkv = 2 * qb + 2;

    const float* Qp = g_q + (size_t)(b * SEQ + q0) * QLD + h * HD;
    const float* Kp = g_k + (size_t)b * SEQ * KLD + kvh * HD;
    const float* Vp = g_v + (size_t)b * SEQ * KLD + kvh * HD;

#pragma unroll
    for (int i = 0; i < 16; i++) {
        const int op = tid + i * 256;
        const int row = op >> 5, c = (op & 31) << 2;
        CP_ASYNC16(sbase + (uint32_t)(row * FKSTR + c) * 4u, Qp + (size_t)row * QLD + c);
    }
    CP_COMMIT();
    CP_WAIT(0);
    __syncthreads();

    uint32_t qf[16][4];
#pragma unroll
    for (int ks = 0; ks < 16; ks++) {
        const uint32_t* bp = fsm + (wm + g) * FKSTR + ks * 8 + tg;
        qf[ks][0] = bp[0];
        qf[ks][1] = bp[8 * FKSTR];
        qf[ks][2] = bp[4];
        qf[ks][3] = bp[8 * FKSTR + 4];
    }
    __syncthreads();

    const uint32_t* kbuf0 = fsm;
    const uint32_t* kbuf1 = fsm + FK_U32;
    const uint32_t* vbuf0 = fsm + 2 * FK_U32;
    const uint32_t* vbuf1 = vbuf0 + FV_U32;
    const uint32_t kbu[2] = { sbase, sbase + FK_U32 * 4u };
    const uint32_t vbu[2] = { sbase + 2u * FK_U32 * 4u, sbase + 2u * FK_U32 * 4u + FV_U32 * 4u };

#define LOAD_KV(t) do {                                                        \
        const int kv0_ = (t) * 64, p_ = (t) & 1;                               \
        _Pragma("unroll")                                                      \
        for (int i_ = 0; i_ < 8; i_++) {                                       \
            const int op_ = tid + i_ * 256;                                    \
            const int row_ = op_ >> 5, c_ = (op_ & 31) << 2;                   \
            CP_ASYNC16(kbu[p_] + (uint32_t)(row_ * FKSTR + c_) * 4u,           \
                       Kp + (size_t)(kv0_ + row_) * KLD + c_);                 \
            CP_ASYNC16(vbu[p_] + (uint32_t)(row_ * FVSTR + c_) * 4u,           \
                       Vp + (size_t)(kv0_ + row_) * KLD + c_);                 \
        }                                                                      \
        CP_COMMIT();                                                           \
    } while (0)

    LOAD_KV(0);
    LOAD_KV(1);

    float mrow0 = -1e30f, mrow1 = -1e30f;
    float lrow0 = 0.f, lrow1 = 0.f;
    float o[16][4];
#pragma unroll
    for (int i = 0; i < 16; i++)
#pragma unroll
        for (int j = 0; j < 4; j++) o[i][j] = 0.f;

    const int r0g = q0 + wm + g, r1g = r0g + 8;
    const int l1 = (lane & ~3) | (tg >> 1);
    const bool odd = (tg & 1) != 0;

    for (int t = 0; t < nkv; t++) {
        const int p = t & 1, kv0 = t * 64;
        if (t + 1 < nkv) { CP_WAIT(1); } else { CP_WAIT(0); }
        __syncthreads();

        float sacc[8][4];
#pragma unroll
        for (int nt = 0; nt < 8; nt++)
#pragma unroll
            for (int j = 0; j < 4; j++) sacc[nt][j] = 0.f;

        const uint32_t* kb = p ? kbuf1 : kbuf0;
#pragma unroll
        for (int ks = 0; ks < 16; ks++) {
#pragma unroll
            for (int nt = 0; nt < 8; nt++) {
                uint32_t bf[2];
                const uint32_t* bp = kb + (nt * 8 + g) * FKSTR + ks * 8 + tg;
                bf[0] = bp[0];
                bf[1] = bp[4];
                mma8(sacc[nt], qf[ks], bf);
            }
        }

        float mnew0 = mrow0, mnew1 = mrow1;
        const bool domask = (kv0 + 63 > q0);
#pragma unroll
        for (int nt = 0; nt < 8; nt++) {
            const int c0 = kv0 + nt * 8 + 2 * tg, c1 = c0 + 1;
            float v0 = sacc[nt][0], v1 = sacc[nt][1];
            float v2 = sacc[nt][2], v3 = sacc[nt][3];
            if (domask) {
                if (c0 > r0g) v0 = -1e30f;
                if (c1 > r0g) v1 = -1e30f;
                if (c0 > r1g) v2 = -1e30f;
                if (c1 > r1g) v3 = -1e30f;
            }
            sacc[nt][0] = v0; sacc[nt][1] = v1; sacc[nt][2] = v2; sacc[nt][3] = v3;
            mnew0 = fmaxf(mnew0, fmaxf(v0, v1));
            mnew1 = fmaxf(mnew1, fmaxf(v2, v3));
        }
        mnew0 = fmaxf(mnew0, __shfl_xor_sync(0xffffffffu, mnew0, 1));
        mnew0 = fmaxf(mnew0, __shfl_xor_sync(0xffffffffu, mnew0, 2));
        mnew1 = fmaxf(mnew1, __shfl_xor_sync(0xffffffffu, mnew1, 1));
        mnew1 = fmaxf(mnew1, __shfl_xor_sync(0xffffffffu, mnew1, 2));

        const float f0 = __expf(mrow0 - mnew0);
        const float f1 = __expf(mrow1 - mnew1);

        float rs0 = 0.f, rs1 = 0.f;
#pragma unroll
        for (int nt = 0; nt < 8; nt++) {
            const float e0 = __expf(sacc[nt][0] - mnew0);
            const float e1 = __expf(sacc[nt][1] - mnew0);
            const float e2 = __expf(sacc[nt][2] - mnew1);
            const float e3 = __expf(sacc[nt][3] - mnew1);
            sacc[nt][0] = e0; sacc[nt][1] = e1; sacc[nt][2] = e2; sacc[nt][3] = e3;
            rs0 += e0 + e1;
            rs1 += e2 + e3;
        }
        rs0 += __shfl_xor_sync(0xffffffffu, rs0, 1);
        rs0 += __shfl_xor_sync(0xffffffffu, rs0, 2);
        rs1 += __shfl_xor_sync(0xffffffffu, rs1, 1);
        rs1 += __shfl_xor_sync(0xffffffffu, rs1, 2);

        lrow0 = lrow0 * f0 + rs0;
        lrow1 = lrow1 * f1 + rs1;
        mrow0 = mnew0;
        mrow1 = mnew1;

#pragma unroll
        for (int nt2 = 0; nt2 < 16; nt2++) {
            o[nt2][0] *= f0; o[nt2][1] *= f0;
            o[nt2][2] *= f1; o[nt2][3] *= f1;
        }

        const uint32_t* vb_ = p ? vbuf1 : vbuf0;
#pragma unroll
        for (int ks2 = 0; ks2 < 8; ks2++) {
            const float c0 = sacc[ks2][0], c1 = sacc[ks2][1];
            const float c2 = sacc[ks2][2], c3 = sacc[ks2][3];
            const float v00 = __shfl_sync(0xffffffffu, c0, l1);
            const float v01 = __shfl_sync(0xffffffffu, c1, l1);
            const float v10 = __shfl_sync(0xffffffffu, c2, l1);
            const float v11 = __shfl_sync(0xffffffffu, c3, l1);
            const float w00 = __shfl_sync(0xffffffffu, c0, l1 + 2);
            const float w01 = __shfl_sync(0xffffffffu, c1, l1 + 2);
            const float w10 = __shfl_sync(0xffffffffu, c2, l1 + 2);
            const float w11 = __shfl_sync(0xffffffffu, c3, l1 + 2);
            uint32_t pa[4];
            pa[0] = f2tf(odd ? v01 : v00);
            pa[1] = f2tf(odd ? v11 : v10);
            pa[2] = f2tf(odd ? w01 : w00);
            pa[3] = f2tf(odd ? w11 : w10);
#pragma unroll
            for (int nt2 = 0; nt2 < 16; nt2++) {
                uint32_t bf[2];
                const uint32_t* bp = vb_ + (ks2 * 8 + tg) * FVSTR + nt2 * 8 + g;
                bf[0] = bp[0];
                bf[1] = bp[4 * FVSTR];
                mma8(o[nt2], pa, bf);
            }
        }

        __syncthreads();
        if (t + 2 < nkv) LOAD_KV(t + 2);
    }

    const float inv0 = 1.f / lrow0;
    const float inv1 = 1.f / lrow1;
    float* orow0 = g_attn + (size_t)(b * SEQ + r0g) * QLD + h * HD;
    float* orow1 = g_attn + (size_t)(b * SEQ + r1g) * QLD + h * HD;
#pragma unroll
    for (int nt2 = 0; nt2 < 16; nt2++) {
        const int c = nt2 * 8 + 2 * tg;
        *(float2*)(orow0 + c) = make_float2(round_tf(o[nt2][0] * inv0),
                                            round_tf(o[nt2][1] * inv0));
        *(float2*)(orow1 + c) = make_float2(round_tf(o[nt2][2] * inv1),
                                            round_tf(o[nt2][3] * inv1));
    }
#undef LOAD_KV
}

// ---------------- RoPE (writes tf32-rounded; q also scaled by 1/sqrt(HD)) -----
__global__ void rope_q(const float* __restrict__ cosT, const float* __restrict__ sinT) {
    const int row = blockIdx.x;
    const int s = row & (SEQ - 1);
    const float sc = 0.08838834764831845f;   // 1/sqrt(128)
    const float* cr = cosT + (size_t)s * HD;
    const float* sr = sinT + (size_t)s * HD;
    float* base = g_q + (size_t)row * QLD;
    for (int idx = threadIdx.x; idx < NH * 64; idx += blockDim.x) {
        const int hh = idx >> 6, d = idx & 63;
        float* p = base + hh * HD;
        const float x1 = p[d], x2 = p[d + 64];
        p[d]      = round_tf((x1 * cr[d]      - x2 * sr[d])      * sc);
        p[d + 64] = round_tf((x2 * cr[d + 64] + x1 * sr[d + 64]) * sc);
    }
}
__global__ void rope_k(const float* __restrict__ cosT, const float* __restrict__ sinT) {
    const int row = blockIdx.x;
    const int s = row & (SEQ - 1);
    const float* cr = cosT + (size_t)s * HD;
    const float* sr = sinT + (size_t)s * HD;
    float* base = g_k + (size_t)row * KLD;
    for (int idx = threadIdx.x; idx < NKV * 64; idx += blockDim.x) {
        const int hh = idx >> 6, d = idx & 63;
        float* p = base + hh * HD;
        const float x1 = p[d], x2 = p[d + 64];
        p[d]      = round_tf(x1 * cr[d]      - x2 * sr[d]);
        p[d + 64] = round_tf(x2 * cr[d + 64] + x1 * sr[d + 64]);
    }
}

// ---------------- launch -----------------------------------------------------
extern "C" void kernel_launch(void* const* d_in, const int* in_sizes, int n_in,
                              void* d_out, int out_size) {
    (void)in_sizes; (void)n_in; (void)out_size;
    const float* hs   = (const float*)d_in[0];
    const float* Wq   = (const float*)d_in[1];
    const float* Wk   = (const float*)d_in[2];
    const float* Wv   = (const float*)d_in[3];
    const float* Wo   = (const float*)d_in[4];
    const float* cosT = (const float*)d_in[5];
    const float* sinT = (const float*)d_in[6];
    float* out = (float*)d_out;

    static bool attr_set = false;
    if (!attr_set) {
        cudaFuncSetAttribute(k_proj_q,   cudaFuncAttributeMaxDynamicSharedMemorySize, PSMEM);
        cudaFuncSetAttribute(k_proj_k,   cudaFuncAttributeMaxDynamicSharedMemorySize, PSMEM);
        cudaFuncSetAttribute(k_proj_v,   cudaFuncAttributeMaxDynamicSharedMemorySize, PSMEM);
        cudaFuncSetAttribute(k_out_proj, cudaFuncAttributeMaxDynamicSharedMemorySize, PSMEM);
        cudaFuncSetAttribute(k_flash,    cudaFuncAttributeMaxDynamicSharedMemorySize, FSMEM);
        attr_set = true;
    }

    k_proj_q<<<dim3(QLD / 128, ROWS / 256), 256, PSMEM>>>(hs, Wq);
    k_proj_k<<<dim3(KLD / 128, ROWS / 256), 256, PSMEM>>>(hs, Wk);
    k_proj_v<<<dim3(KLD / 128, ROWS / 256), 256, PSMEM>>>(hs, Wv);
    rope_q<<<ROWS, 256>>>(cosT, sinT);
    rope_k<<<ROWS, 256>>>(cosT, sinT);
    k_flash<<<dim3(SEQ / 128, NBH), 256, FSMEM>>>();
    k_out_proj<<<dim3(HDIM / 128, ROWS / 256), 256, PSMEM>>>(Wo, out);
}

// round 6
// speedup vs baseline: 1.2425x; 1.2425x over previous
#include <cuda_runtime.h>
#include <cstdint>

#define SEQ 2048
#define NB 2
#define ROWS (NB * SEQ)      // 4096 total (b,s) rows
#define HDIM 4096
#define NH 32
#define NKV 8
#define HD 128
#define QLD (NH * HD)        // 4096
#define KLD (NKV * HD)       // 1024
#define NBH (NB * NH)        // 64

// ---------------- scratch (static device allocations; no cudaMalloc) -------
__device__ float g_q[(size_t)ROWS * QLD];                 // 64 MB
__device__ float g_k[(size_t)ROWS * KLD];                 // 16 MB
__device__ float g_v[(size_t)ROWS * KLD];                 // 16 MB
__device__ float g_attn[(size_t)ROWS * QLD];              // 64 MB
// tf32-pre-rounded copies of the inputs
__device__ float g_hs[(size_t)ROWS * HDIM];               // 64 MB
__device__ float g_wq[(size_t)QLD * HDIM];                // 64 MB
__device__ float g_wk[(size_t)KLD * HDIM];                // 16 MB
__device__ float g_wv[(size_t)KLD * HDIM];                // 16 MB
__device__ float g_wo[(size_t)HDIM * QLD];                // 64 MB

// ---------------- helpers ---------------------------------------------------
__device__ __forceinline__ uint32_t smem_u32(const void* p) {
    uint32_t a;
    asm("{ .reg .u64 t; cvta.to.shared.u64 t, %1; cvt.u32.u64 %0, t; }" : "=r"(a) : "l"(p));
    return a;
}
__device__ __forceinline__ uint32_t f2tf(float f) {
    uint32_t u;
    asm("cvt.rna.tf32.f32 %0, %1;" : "=r"(u) : "f"(f));
    return u;
}
__device__ __forceinline__ float round_tf(float f) {
    return __uint_as_float(f2tf(f));
}

#define CP_ASYNC16(dst, src) \
    asm volatile("cp.async.cg.shared.global [%0], [%1], 16;" :: "r"(dst), "l"(src) : "memory")
#define CP_COMMIT() asm volatile("cp.async.commit_group;" ::: "memory")
#define CP_WAIT(n)  asm volatile("cp.async.wait_group %0;" :: "n"(n) : "memory")

__device__ __forceinline__ void mma8(float* c, const uint32_t* a, const uint32_t* b) {
    asm volatile(
        "mma.sync.aligned.m16n8k8.row.col.f32.tf32.tf32.f32 "
        "{%0,%1,%2,%3}, {%4,%5,%6,%7}, {%8,%9}, {%0,%1,%2,%3};\n"
        : "+f"(c[0]), "+f"(c[1]), "+f"(c[2]), "+f"(c[3])
        : "r"(a[0]), "r"(a[1]), "r"(a[2]), "r"(a[3]), "r"(b[0]), "r"(b[1]));
}

// ============================================================================
// Projection GEMM: C[128,128] tile = A * B^T, pre-rounded tf32 fp32 operands.
// A [M,K], B [N,K] row-major.  256 threads = 8 warps (4m x 2n), warp 32x64.
// BK=32, 3-stage cp.async pipeline, 2 CTAs/SM.
// ============================================================================
#define PBK 32
#define PSTAGE 3
#define PSTR 36                               // smem row stride (floats)
#define PA_BYTES (128 * PSTR * 4)             // 18432
#define PSTAGE_BYTES (2 * PA_BYTES)           // 36864
#define PSMEM (PSTAGE * PSTAGE_BYTES)         // 110592

template <bool RND>
__device__ __forceinline__ void pgemm(
    const float* __restrict__ A, const float* __restrict__ B, float* __restrict__ C,
    int m0, int n0, int K, int lda, int ldb, int ldc)
{
    extern __shared__ float dsm[];
    const uint32_t sbase = smem_u32(dsm);

    const int tid = threadIdx.x;
    const int arow = tid >> 3;          // 0..31 (rows arow + 32*i)
    const int acol = (tid & 7) << 2;    // 0,4,...,28

    const int warp = tid >> 5;
    const int lane = tid & 31;
    const int wm = (warp & 3) << 5;     // 0,32,64,96
    const int wn = (warp >> 2) << 6;    // 0,64
    const int g  = lane >> 2;
    const int tg = lane & 3;

    float acc[2][8][4];
#pragma unroll
    for (int i = 0; i < 2; i++)
#pragma unroll
        for (int j = 0; j < 8; j++)
#pragma unroll
            for (int l = 0; l < 4; l++) acc[i][j][l] = 0.f;

    const int nk = K / PBK;

#define PLOAD(s) do {                                                              \
        const uint32_t sa_u = sbase + (uint32_t)((s) % PSTAGE) * PSTAGE_BYTES;     \
        const uint32_t sb_u = sa_u + PA_BYTES;                                     \
        const float* pa_ = A + (size_t)(m0 + arow) * lda + (s) * PBK + acol;       \
        const float* pb_ = B + (size_t)(n0 + arow) * ldb + (s) * PBK + acol;       \
        _Pragma("unroll")                                                          \
        for (int r_ = 0; r_ < 128; r_ += 32) {                                     \
            CP_ASYNC16(sa_u + (uint32_t)((arow + r_) * PSTR + acol) * 4u,          \
                       pa_ + (size_t)r_ * lda);                                    \
            CP_ASYNC16(sb_u + (uint32_t)((arow + r_) * PSTR + acol) * 4u,          \
                       pb_ + (size_t)r_ * ldb);                                    \
        }                                                                          \
    } while (0)

#pragma unroll
    for (int s = 0; s < PSTAGE - 1; s++) {
        if (s < nk) PLOAD(s);
        CP_COMMIT();
    }

    for (int kt = 0; kt < nk; kt++) {
        CP_WAIT(PSTAGE - 2);
        __syncthreads();
        if (kt + PSTAGE - 1 < nk) PLOAD(kt + PSTAGE - 1);
        CP_COMMIT();

        const uint32_t* sa = (const uint32_t*)dsm + (size_t)(kt % PSTAGE) * (PSTAGE_BYTES / 4);
        const uint32_t* sb = sa + PA_BYTES / 4;

#pragma unroll
        for (int ks = 0; ks < 4; ks++) {
            const int kb = ks * 8;
            uint32_t af[2][4];
#pragma unroll
            for (int mt = 0; mt < 2; mt++) {
                const uint32_t* base = &sa[(wm + mt * 16 + g) * PSTR + kb + tg];
                af[mt][0] = base[0];
                af[mt][1] = base[8 * PSTR];
                af[mt][2] = base[4];
                af[mt][3] = base[8 * PSTR + 4];
            }
            uint32_t bf[8][2];
#pragma unroll
            for (int nt = 0; nt < 8; nt++) {
                const uint32_t* base = &sb[(wn + nt * 8 + g) * PSTR + kb + tg];
                bf[nt][0] = base[0];
                bf[nt][1] = base[4];
            }
#pragma unroll
            for (int mt = 0; mt < 2; mt++)
#pragma unroll
                for (int nt = 0; nt < 8; nt++)
                    mma8(acc[mt][nt], af[mt], bf[nt]);
        }
        __syncthreads();
    }

#pragma unroll
    for (int mt = 0; mt < 2; mt++) {
        const int r = m0 + wm + mt * 16 + g;
#pragma unroll
        for (int nt = 0; nt < 8; nt++) {
            const int c = n0 + wn + nt * 8 + (tg << 1);
            float v0 = acc[mt][nt][0], v1 = acc[mt][nt][1];
            float v2 = acc[mt][nt][2], v3 = acc[mt][nt][3];
            if (RND) {
                v0 = round_tf(v0); v1 = round_tf(v1);
                v2 = round_tf(v2); v3 = round_tf(v3);
            }
            float* p0 = C + (size_t)r * ldc + c;
            *(float2*)p0 = make_float2(v0, v1);
            float* p1 = p0 + (size_t)8 * ldc;
            *(float2*)p1 = make_float2(v2, v3);
        }
    }
#undef PLOAD
}

// ---------------- projection wrappers ----------------------------------------
__global__ void __launch_bounds__(256, 2) k_proj_q() {
    pgemm<false>(g_hs, g_wq, g_q, blockIdx.y * 128, blockIdx.x * 128, HDIM, HDIM, HDIM, QLD);
}
__global__ void __launch_bounds__(256, 2) k_proj_k() {
    pgemm<false>(g_hs, g_wk, g_k, blockIdx.y * 128, blockIdx.x * 128, HDIM, HDIM, HDIM, KLD);
}
__global__ void __launch_bounds__(256, 2) k_proj_v() {
    pgemm<true>(g_hs, g_wv, g_v, blockIdx.y * 128, blockIdx.x * 128, HDIM, HDIM, HDIM, KLD);
}
__global__ void __launch_bounds__(256, 2) k_out_proj(float* __restrict__ out) {
    pgemm<false>(g_attn, g_wo, out, blockIdx.y * 128, blockIdx.x * 128, QLD, QLD, HDIM, HDIM);
}

// ============================================================================
// Fused flash attention (causal, online softmax).
// Grid (16 q-blocks [reversed], 64 z).  256 threads = 8 warps, 16 Q rows each.
// Q is pre-scaled by 1/sqrt(HD) in rope_q.
// ============================================================================
#define FKSTR 132
#define FVSTR 136
#define FK_U32 (64 * FKSTR)       // 8448
#define FV_U32 (64 * FVSTR)       // 8704
#define FSMEM ((2 * FK_U32 + 2 * FV_U32) * 4)   // 137216 bytes

__global__ void __launch_bounds__(256, 1) k_flash() {
    extern __shared__ uint32_t fsm[];
    const uint32_t sbase = smem_u32(fsm);

    const int tid = threadIdx.x;
    const int wid = tid >> 5, lane = tid & 31;
    const int g = lane >> 2, tg = lane & 3;
    const int wm = wid * 16;

    const int z = blockIdx.y, b = z >> 5, h = z & 31, kvh = h >> 2;
    const int qb = (int)(gridDim.x - 1 - blockIdx.x);
    const int q0 = qb * 128;
    const int nkv = 2 * qb + 2;

    const float* Qp = g_q + (size_t)(b * SEQ + q0) * QLD + h * HD;
    const float* Kp = g_k + (size_t)b * SEQ * KLD + kvh * HD;
    const float* Vp = g_v + (size_t)b * SEQ * KLD + kvh * HD;

#pragma unroll
    for (int i = 0; i < 16; i++) {
        const int op = tid + i * 256;
        const int row = op >> 5, c = (op & 31) << 2;
        CP_ASYNC16(sbase + (uint32_t)(row * FKSTR + c) * 4u, Qp + (size_t)row * QLD + c);
    }
    CP_COMMIT();
    CP_WAIT(0);
    __syncthreads();

    uint32_t qf[16][4];
#pragma unroll
    for (int ks = 0; ks < 16; ks++) {
        const uint32_t* bp = fsm + (wm + g) * FKSTR + ks * 8 + tg;
        qf[ks][0] = bp[0];
        qf[ks][1] = bp[8 * FKSTR];
        qf[ks][2] = bp[4];
        qf[ks][3] = bp[8 * FKSTR + 4];
    }
    __syncthreads();

    const uint32_t* kbuf0 = fsm;
    const uint32_t* kbuf1 = fsm + FK_U32;
    const uint32_t* vbuf0 = fsm + 2 * FK_U32;
    const uint32_t* vbuf1 = vbuf0 + FV_U32;
    const uint32_t kbu[2] = { sbase, sbase + FK_U32 * 4u };
    const uint32_t vbu[2] = { sbase + 2u * FK_U32 * 4u, sbase + 2u * FK_U32 * 4u + FV_U32 * 4u };

#define LOAD_KV(t) do {                                                        \
        const int kv0_ = (t) * 64, p_ = (t) & 1;                               \
        _Pragma("unroll")                                                      \
        for (int i_ = 0; i_ < 8; i_++) {                                       \
            const int op_ = tid + i_ * 256;                                    \
            const int row_ = op_ >> 5, c_ = (op_ & 31) << 2;                   \
            CP_ASYNC16(kbu[p_] + (uint32_t)(row_ * FKSTR + c_) * 4u,           \
                       Kp + (size_t)(kv0_ + row_) * KLD + c_);                 \
            CP_ASYNC16(vbu[p_] + (uint32_t)(row_ * FVSTR + c_) * 4u,           \
                       Vp + (size_t)(kv0_ + row_) * KLD + c_);                 \
        }                                                                      \
        CP_COMMIT();                                                           \
    } while (0)

    LOAD_KV(0);
    LOAD_KV(1);

    float mrow0 = -1e30f, mrow1 = -1e30f;
    float lrow0 = 0.f, lrow1 = 0.f;
    float o[16][4];
#pragma unroll
    for (int i = 0; i < 16; i++)
#pragma unroll
        for (int j = 0; j < 4; j++) o[i][j] = 0.f;

    const int r0g = q0 + wm + g, r1g = r0g + 8;
    const int l1 = (lane & ~3) | (tg >> 1);
    const bool odd = (tg & 1) != 0;

    for (int t = 0; t < nkv; t++) {
        const int p = t & 1, kv0 = t * 64;
        if (t + 1 < nkv) { CP_WAIT(1); } else { CP_WAIT(0); }
        __syncthreads();

        float sacc[8][4];
#pragma unroll
        for (int nt = 0; nt < 8; nt++)
#pragma unroll
            for (int j = 0; j < 4; j++) sacc[nt][j] = 0.f;

        const uint32_t* kb = p ? kbuf1 : kbuf0;
#pragma unroll
        for (int ks = 0; ks < 16; ks++) {
#pragma unroll
            for (int nt = 0; nt < 8; nt++) {
                uint32_t bf[2];
                const uint32_t* bp = kb + (nt * 8 + g) * FKSTR + ks * 8 + tg;
                bf[0] = bp[0];
                bf[1] = bp[4];
                mma8(sacc[nt], qf[ks], bf);
            }
        }

        float mnew0 = mrow0, mnew1 = mrow1;
        const bool domask = (kv0 + 63 > q0);
#pragma unroll
        for (int nt = 0; nt < 8; nt++) {
            const int c0 = kv0 + nt * 8 + 2 * tg, c1 = c0 + 1;
            float v0 = sacc[nt][0], v1 = sacc[nt][1];
            float v2 = sacc[nt][2], v3 = sacc[nt][3];
            if (domask) {
                if (c0 > r0g) v0 = -1e30f;
                if (c1 > r0g) v1 = -1e30f;
                if (c0 > r1g) v2 = -1e30f;
                if (c1 > r1g) v3 = -1e30f;
            }
            sacc[nt][0] = v0; sacc[nt][1] = v1; sacc[nt][2] = v2; sacc[nt][3] = v3;
            mnew0 = fmaxf(mnew0, fmaxf(v0, v1));
            mnew1 = fmaxf(mnew1, fmaxf(v2, v3));
        }
        mnew0 = fmaxf(mnew0, __shfl_xor_sync(0xffffffffu, mnew0, 1));
        mnew0 = fmaxf(mnew0, __shfl_xor_sync(0xffffffffu, mnew0, 2));
        mnew1 = fmaxf(mnew1, __shfl_xor_sync(0xffffffffu, mnew1, 1));
        mnew1 = fmaxf(mnew1, __shfl_xor_sync(0xffffffffu, mnew1, 2));

        const float f0 = __expf(mrow0 - mnew0);
        const float f1 = __expf(mrow1 - mnew1);

        float rs0 = 0.f, rs1 = 0.f;
#pragma unroll
        for (int nt = 0; nt < 8; nt++) {
            const float e0 = __expf(sacc[nt][0] - mnew0);
            const float e1 = __expf(sacc[nt][1] - mnew0);
            const float e2 = __expf(sacc[nt][2] - mnew1);
            const float e3 = __expf(sacc[nt][3] - mnew1);
            sacc[nt][0] = e0; sacc[nt][1] = e1; sacc[nt][2] = e2; sacc[nt][3] = e3;
            rs0 += e0 + e1;
            rs1 += e2 + e3;
        }
        rs0 += __shfl_xor_sync(0xffffffffu, rs0, 1);
        rs0 += __shfl_xor_sync(0xffffffffu, rs0, 2);
        rs1 += __shfl_xor_sync(0xffffffffu, rs1, 1);
        rs1 += __shfl_xor_sync(0xffffffffu, rs1, 2);

        lrow0 = lrow0 * f0 + rs0;
        lrow1 = lrow1 * f1 + rs1;
        mrow0 = mnew0;
        mrow1 = mnew1;

#pragma unroll
        for (int nt2 = 0; nt2 < 16; nt2++) {
            o[nt2][0] *= f0; o[nt2][1] *= f0;
            o[nt2][2] *= f1; o[nt2][3] *= f1;
        }

        const uint32_t* vb_ = p ? vbuf1 : vbuf0;
#pragma unroll
        for (int ks2 = 0; ks2 < 8; ks2++) {
            const float c0 = sacc[ks2][0], c1 = sacc[ks2][1];
            const float c2 = sacc[ks2][2], c3 = sacc[ks2][3];
            const float v00 = __shfl_sync(0xffffffffu, c0, l1);
            const float v01 = __shfl_sync(0xffffffffu, c1, l1);
            const float v10 = __shfl_sync(0xffffffffu, c2, l1);
            const float v11 = __shfl_sync(0xffffffffu, c3, l1);
            const float w00 = __shfl_sync(0xffffffffu, c0, l1 + 2);
            const float w01 = __shfl_sync(0xffffffffu, c1, l1 + 2);
            const float w10 = __shfl_sync(0xffffffffu, c2, l1 + 2);
            const float w11 = __shfl_sync(0xffffffffu, c3, l1 + 2);
            uint32_t pa[4];
            pa[0] = f2tf(odd ? v01 : v00);
            pa[1] = f2tf(odd ? v11 : v10);
            pa[2] = f2tf(odd ? w01 : w00);
            pa[3] = f2tf(odd ? w11 : w10);
#pragma unroll
            for (int nt2 = 0; nt2 < 16; nt2++) {
                uint32_t bf[2];
                const uint32_t* bp = vb_ + (ks2 * 8 + tg) * FVSTR + nt2 * 8 + g;
                bf[0] = bp[0];
                bf[1] = bp[4 * FVSTR];
                mma8(o[nt2], pa, bf);
            }
        }

        __syncthreads();
        if (t + 2 < nkv) LOAD_KV(t + 2);
    }

    const float inv0 = 1.f / lrow0;
    const float inv1 = 1.f / lrow1;
    float* orow0 = g_attn + (size_t)(b * SEQ + r0g) * QLD + h * HD;
    float* orow1 = g_attn + (size_t)(b * SEQ + r1g) * QLD + h * HD;
#pragma unroll
    for (int nt2 = 0; nt2 < 16; nt2++) {
        const int c = nt2 * 8 + 2 * tg;
        *(float2*)(orow0 + c) = make_float2(round_tf(o[nt2][0] * inv0),
                                            round_tf(o[nt2][1] * inv0));
        *(float2*)(orow1 + c) = make_float2(round_tf(o[nt2][2] * inv1),
                                            round_tf(o[nt2][3] * inv1));
    }
#undef LOAD_KV
}

// ---------------- tf32 rounding prepass (MLP=4, exact coverage) --------------
// grid = n_float4 / 1024, block = 256; each thread handles 4 float4s.
__global__ void round_copy4(float4* __restrict__ dst, const float4* __restrict__ src) {
    const size_t base = (size_t)blockIdx.x * 1024 + threadIdx.x;
    float4 a = src[base];
    float4 b = src[base + 256];
    float4 c = src[base + 512];
    float4 d = src[base + 768];
    a.x = round_tf(a.x); a.y = round_tf(a.y); a.z = round_tf(a.z); a.w = round_tf(a.w);
    b.x = round_tf(b.x); b.y = round_tf(b.y); b.z = round_tf(b.z); b.w = round_tf(b.w);
    c.x = round_tf(c.x); c.y = round_tf(c.y); c.z = round_tf(c.z); c.w = round_tf(c.w);
    d.x = round_tf(d.x); d.y = round_tf(d.y); d.z = round_tf(d.z); d.w = round_tf(d.w);
    dst[base]       = a;
    dst[base + 256] = b;
    dst[base + 512] = c;
    dst[base + 768] = d;
}

// ---------------- RoPE (writes tf32-rounded; q also scaled by 1/sqrt(HD)) -----
__global__ void rope_q(const float* __restrict__ cosT, const float* __restrict__ sinT) {
    const int row = blockIdx.x;
    const int s = row & (SEQ - 1);
    const float sc = 0.08838834764831845f;   // 1/sqrt(128)
    const float* cr = cosT + (size_t)s * HD;
    const float* sr = sinT + (size_t)s * HD;
    float* base = g_q + (size_t)row * QLD;
    for (int idx = threadIdx.x; idx < NH * 64; idx += blockDim.x) {
        const int hh = idx >> 6, d = idx & 63;
        float* p = base + hh * HD;
        const float x1 = p[d], x2 = p[d + 64];
        p[d]      = round_tf((x1 * cr[d]      - x2 * sr[d])      * sc);
        p[d + 64] = round_tf((x2 * cr[d + 64] + x1 * sr[d + 64]) * sc);
    }
}
__global__ void rope_k(const float* __restrict__ cosT, const float* __restrict__ sinT) {
    const int row = blockIdx.x;
    const int s = row & (SEQ - 1);
    const float* cr = cosT + (size_t)s * HD;
    const float* sr = sinT + (size_t)s * HD;
    float* base = g_k + (size_t)row * KLD;
    for (int idx = threadIdx.x; idx < NKV * 64; idx += blockDim.x) {
        const int hh = idx >> 6, d = idx & 63;
        float* p = base + hh * HD;
        const float x1 = p[d], x2 = p[d + 64];
        p[d]      = round_tf(x1 * cr[d]      - x2 * sr[d]);
        p[d + 64] = round_tf(x2 * cr[d + 64] + x1 * sr[d + 64]);
    }
}

// ---------------- launch -----------------------------------------------------
extern "C" void kernel_launch(void* const* d_in, const int* in_sizes, int n_in,
                              void* d_out, int out_size) {
    (void)in_sizes; (void)n_in; (void)out_size;
    const float* hs   = (const float*)d_in[0];
    const float* Wq   = (const float*)d_in[1];
    const float* Wk   = (const float*)d_in[2];
    const float* Wv   = (const float*)d_in[3];
    const float* Wo   = (const float*)d_in[4];
    const float* cosT = (const float*)d_in[5];
    const float* sinT = (const float*)d_in[6];
    float* out = (float*)d_out;

    static bool attr_set = false;
    if (!attr_set) {
        cudaFuncSetAttribute(k_proj_q,   cudaFuncAttributeMaxDynamicSharedMemorySize, PSMEM);
        cudaFuncSetAttribute(k_proj_k,   cudaFuncAttributeMaxDynamicSharedMemorySize, PSMEM);
        cudaFuncSetAttribute(k_proj_v,   cudaFuncAttributeMaxDynamicSharedMemorySize, PSMEM);
        cudaFuncSetAttribute(k_out_proj, cudaFuncAttributeMaxDynamicSharedMemorySize, PSMEM);
        cudaFuncSetAttribute(k_flash,    cudaFuncAttributeMaxDynamicSharedMemorySize, FSMEM);
        attr_set = true;
    }

    float* phs;  cudaGetSymbolAddress((void**)&phs, g_hs);
    float* pwq;  cudaGetSymbolAddress((void**)&pwq, g_wq);
    float* pwk;  cudaGetSymbolAddress((void**)&pwk, g_wk);
    float* pwv;  cudaGetSymbolAddress((void**)&pwv, g_wv);
    float* pwo;  cudaGetSymbolAddress((void**)&pwo, g_wo);

    // n_float4 / 1024 blocks; all sizes divide exactly
    round_copy4<<<((size_t)ROWS * HDIM / 4) / 1024, 256>>>((float4*)phs, (const float4*)hs);
    round_copy4<<<((size_t)QLD * HDIM / 4) / 1024, 256>>>((float4*)pwq, (const float4*)Wq);
    round_copy4<<<((size_t)KLD * HDIM / 4) / 1024, 256>>>((float4*)pwk, (const float4*)Wk);
    round_copy4<<<((size_t)KLD * HDIM / 4) / 1024, 256>>>((float4*)pwv, (const float4*)Wv);
    round_copy4<<<((size_t)HDIM * QLD / 4) / 1024, 256>>>((float4*)pwo, (const float4*)Wo);

    k_proj_q<<<dim3(QLD / 128, ROWS / 128), 256, PSMEM>>>();
    k_proj_k<<<dim3(KLD / 128, ROWS / 128), 256, PSMEM>>>();
    k_proj_v<<<dim3(KLD / 128, ROWS / 128), 256, PSMEM>>>();
    rope_q<<<ROWS, 256>>>(cosT, sinT);
    rope_k<<<ROWS, 256>>>(cosT, sinT);
    k_flash<<<dim3(SEQ / 128, NBH), 256, FSMEM>>>();
    k_out_proj<<<dim3(HDIM / 128, ROWS / 128), 256, PSMEM>>>(out);
}

// round 7
// speedup vs baseline: 1.3017x; 1.0477x over previous
#include <cuda_runtime.h>
#include <cstdint>

#define SEQ 2048
#define NB 2
#define ROWS (NB * SEQ)      // 4096 total (b,s) rows
#define HDIM 4096
#define NH 32
#define NKV 8
#define HD 128
#define QLD (NH * HD)        // 4096
#define KLD (NKV * HD)       // 1024
#define NBH (NB * NH)        // 64

// ---------------- scratch (static device allocations; no cudaMalloc) -------
__device__ float g_q[(size_t)ROWS * QLD];                 // 64 MB
__device__ float g_k[(size_t)ROWS * KLD];                 // 16 MB
__device__ float g_v[(size_t)ROWS * KLD];                 // 16 MB
__device__ float g_attn[(size_t)ROWS * QLD];              // 64 MB
// tf32-pre-rounded copies of the inputs
__device__ float g_hs[(size_t)ROWS * HDIM];               // 64 MB
__device__ float g_wq[(size_t)QLD * HDIM];                // 64 MB
__device__ float g_wk[(size_t)KLD * HDIM];                // 16 MB
__device__ float g_wv[(size_t)KLD * HDIM];                // 16 MB
__device__ float g_wo[(size_t)HDIM * QLD];                // 64 MB

// ---------------- helpers ---------------------------------------------------
__device__ __forceinline__ uint32_t smem_u32(const void* p) {
    uint32_t a;
    asm("{ .reg .u64 t; cvta.to.shared.u64 t, %1; cvt.u32.u64 %0, t; }" : "=r"(a) : "l"(p));
    return a;
}
__device__ __forceinline__ uint32_t f2tf(float f) {
    uint32_t u;
    asm("cvt.rna.tf32.f32 %0, %1;" : "=r"(u) : "f"(f));
    return u;
}
__device__ __forceinline__ float round_tf(float f) {
    return __uint_as_float(f2tf(f));
}

#define CP_ASYNC16(dst, src) \
    asm volatile("cp.async.cg.shared.global [%0], [%1], 16;" :: "r"(dst), "l"(src) : "memory")
#define CP_COMMIT() asm volatile("cp.async.commit_group;" ::: "memory")
#define CP_WAIT(n)  asm volatile("cp.async.wait_group %0;" :: "n"(n) : "memory")

__device__ __forceinline__ void mma8(float* c, const uint32_t* a, const uint32_t* b) {
    asm volatile(
        "mma.sync.aligned.m16n8k8.row.col.f32.tf32.tf32.f32 "
        "{%0,%1,%2,%3}, {%4,%5,%6,%7}, {%8,%9}, {%0,%1,%2,%3};\n"
        : "+f"(c[0]), "+f"(c[1]), "+f"(c[2]), "+f"(c[3])
        : "r"(a[0]), "r"(a[1]), "r"(a[2]), "r"(a[3]), "r"(b[0]), "r"(b[1]));
}

// ============================================================================
// Projection GEMM: C[128,128] tile = A * B^T, pre-rounded tf32 fp32 operands.
// A [M,K], B [N,K] row-major.  128 threads = 4 warps (2m x 2n), warp 64x64.
// BK=32, 3-stage cp.async pipeline, 2 CTAs/SM.
// ============================================================================
#define PBK 32
#define PSTAGE 3
#define PSTR 36                               // smem row stride (floats)
#define PA_BYTES (128 * PSTR * 4)             // 18432
#define PSTAGE_BYTES (2 * PA_BYTES)           // 36864
#define PSMEM (PSTAGE * PSTAGE_BYTES)         // 110592

__device__ __noinline__ void pgemm(
    const float* __restrict__ A, const float* __restrict__ B, float* __restrict__ C,
    int m0, int n0, int K, int lda, int ldb, int ldc, bool rnd)
{
    extern __shared__ float dsm[];
    const uint32_t sbase = smem_u32(dsm);

    const int tid = threadIdx.x;
    const int arow = tid >> 3;          // 0..15 (rows arow + 16*i)
    const int acol = (tid & 7) << 2;    // 0,4,...,28

    const int warp = tid >> 5;
    const int lane = tid & 31;
    const int wm = (warp & 1) << 6;     // 0,64
    const int wn = (warp >> 1) << 6;    // 0,64
    const int g  = lane >> 2;
    const int tg = lane & 3;

    float acc[4][8][4];
#pragma unroll
    for (int i = 0; i < 4; i++)
#pragma unroll
        for (int j = 0; j < 8; j++)
#pragma unroll
            for (int l = 0; l < 4; l++) acc[i][j][l] = 0.f;

    const int nk = K / PBK;

#define PLOAD(s) do {                                                              \
        const uint32_t sa_u = sbase + (uint32_t)((s) % PSTAGE) * PSTAGE_BYTES;     \
        const uint32_t sb_u = sa_u + PA_BYTES;                                     \
        const float* pa_ = A + (size_t)(m0 + arow) * lda + (s) * PBK + acol;       \
        const float* pb_ = B + (size_t)(n0 + arow) * ldb + (s) * PBK + acol;       \
        _Pragma("unroll")                                                          \
        for (int r_ = 0; r_ < 128; r_ += 16) {                                     \
            CP_ASYNC16(sa_u + (uint32_t)((arow + r_) * PSTR + acol) * 4u,          \
                       pa_ + (size_t)r_ * lda);                                    \
            CP_ASYNC16(sb_u + (uint32_t)((arow + r_) * PSTR + acol) * 4u,          \
                       pb_ + (size_t)r_ * ldb);                                    \
        }                                                                          \
    } while (0)

#pragma unroll
    for (int s = 0; s < PSTAGE - 1; s++) {
        if (s < nk) PLOAD(s);
        CP_COMMIT();
    }

    for (int kt = 0; kt < nk; kt++) {
        CP_WAIT(PSTAGE - 2);
        __syncthreads();
        if (kt + PSTAGE - 1 < nk) PLOAD(kt + PSTAGE - 1);
        CP_COMMIT();

        const uint32_t* sa = (const uint32_t*)dsm + (size_t)(kt % PSTAGE) * (PSTAGE_BYTES / 4);
        const uint32_t* sb = sa + PA_BYTES / 4;

#pragma unroll
        for (int ks = 0; ks < 4; ks++) {
            const int kb = ks * 8;
            uint32_t af[4][4];
#pragma unroll
            for (int mt = 0; mt < 4; mt++) {
                const uint32_t* base = &sa[(wm + mt * 16 + g) * PSTR + kb + tg];
                af[mt][0] = base[0];
                af[mt][1] = base[8 * PSTR];
                af[mt][2] = base[4];
                af[mt][3] = base[8 * PSTR + 4];
            }
            uint32_t bf[8][2];
#pragma unroll
            for (int nt = 0; nt < 8; nt++) {
                const uint32_t* base = &sb[(wn + nt * 8 + g) * PSTR + kb + tg];
                bf[nt][0] = base[0];
                bf[nt][1] = base[4];
            }
#pragma unroll
            for (int mt = 0; mt < 4; mt++)
#pragma unroll
                for (int nt = 0; nt < 8; nt++)
                    mma8(acc[mt][nt], af[mt], bf[nt]);
        }
        __syncthreads();
    }

#pragma unroll
    for (int mt = 0; mt < 4; mt++) {
        const int r = m0 + wm + mt * 16 + g;
#pragma unroll
        for (int nt = 0; nt < 8; nt++) {
            const int c = n0 + wn + nt * 8 + (tg << 1);
            float v0 = acc[mt][nt][0], v1 = acc[mt][nt][1];
            float v2 = acc[mt][nt][2], v3 = acc[mt][nt][3];
            if (rnd) {
                v0 = round_tf(v0); v1 = round_tf(v1);
                v2 = round_tf(v2); v3 = round_tf(v3);
            }
            float* p0 = C + (size_t)r * ldc + c;
            *(float2*)p0 = make_float2(v0, v1);
            float* p1 = p0 + (size_t)8 * ldc;
            *(float2*)p1 = make_float2(v2, v3);
        }
    }
#undef PLOAD
}

// ---------------- projection wrappers ----------------------------------------
// merged QKV: grid (48, 32); x: [0,32)->Q, [32,40)->K, [40,48)->V (V rounds)
__global__ void __launch_bounds__(128, 2) k_proj_qkv() {
    const int nb = blockIdx.x;
    const int m0 = blockIdx.y * 128;
    if (nb < 32) {
        pgemm(g_hs, g_wq, g_q, m0, nb * 128, HDIM, HDIM, HDIM, QLD, false);
    } else if (nb < 40) {
        pgemm(g_hs, g_wk, g_k, m0, (nb - 32) * 128, HDIM, HDIM, HDIM, KLD, false);
    } else {
        pgemm(g_hs, g_wv, g_v, m0, (nb - 40) * 128, HDIM, HDIM, HDIM, KLD, true);
    }
}
__global__ void __launch_bounds__(128, 2) k_out_proj(float* __restrict__ out) {
    pgemm(g_attn, g_wo, out, blockIdx.y * 128, blockIdx.x * 128, QLD, QLD, HDIM, HDIM, false);
}

// ============================================================================
// Fused flash attention (causal, online softmax).
// Grid (16 q-blocks [reversed], 64 z).  256 threads = 8 warps, 16 Q rows each.
// Q is pre-scaled by 1/sqrt(HD) in rope_q.
// ============================================================================
#define FKSTR 132
#define FVSTR 136
#define FK_U32 (64 * FKSTR)       // 8448
#define FV_U32 (64 * FVSTR)       // 8704
#define FSMEM ((2 * FK_U32 + 2 * FV_U32) * 4)   // 137216 bytes

__global__ void __launch_bounds__(256, 1) k_flash() {
    extern __shared__ uint32_t fsm[];
    const uint32_t sbase = smem_u32(fsm);

    const int tid = threadIdx.x;
    const int wid = tid >> 5, lane = tid & 31;
    const int g = lane >> 2, tg = lane & 3;
    const int wm = wid * 16;

    const int z = blockIdx.y, b = z >> 5, h = z & 31, kvh = h >> 2;
    const int qb = (int)(gridDim.x - 1 - blockIdx.x);
    const int q0 = qb * 128;
    const int nkv = 2 * qb + 2;

    const float* Qp = g_q + (size_t)(b * SEQ + q0) * QLD + h * HD;
    const float* Kp = g_k + (size_t)b * SEQ * KLD + kvh * HD;
    const float* Vp = g_v + (size_t)b * SEQ * KLD + kvh * HD;

#pragma unroll
    for (int i = 0; i < 16; i++) {
        const int op = tid + i * 256;
        const int row = op >> 5, c = (op & 31) << 2;
        CP_ASYNC16(sbase + (uint32_t)(row * FKSTR + c) * 4u, Qp + (size_t)row * QLD + c);
    }
    CP_COMMIT();
    CP_WAIT(0);
    __syncthreads();

    uint32_t qf[16][4];
#pragma unroll
    for (int ks = 0; ks < 16; ks++) {
        const uint32_t* bp = fsm + (wm + g) * FKSTR + ks * 8 + tg;
        qf[ks][0] = bp[0];
        qf[ks][1] = bp[8 * FKSTR];
        qf[ks][2] = bp[4];
        qf[ks][3] = bp[8 * FKSTR + 4];
    }
    __syncthreads();

    const uint32_t* kbuf0 = fsm;
    const uint32_t* kbuf1 = fsm + FK_U32;
    const uint32_t* vbuf0 = fsm + 2 * FK_U32;
    const uint32_t* vbuf1 = vbuf0 + FV_U32;
    const uint32_t kbu[2] = { sbase, sbase + FK_U32 * 4u };
    const uint32_t vbu[2] = { sbase + 2u * FK_U32 * 4u, sbase + 2u * FK_U32 * 4u + FV_U32 * 4u };

#define LOAD_KV(t) do {                                                        \
        const int kv0_ = (t) * 64, p_ = (t) & 1;                               \
        _Pragma("unroll")                                                      \
        for (int i_ = 0; i_ < 8; i_++) {                                       \
            const int op_ = tid + i_ * 256;                                    \
            const int row_ = op_ >> 5, c_ = (op_ & 31) << 2;                   \
            CP_ASYNC16(kbu[p_] + (uint32_t)(row_ * FKSTR + c_) * 4u,           \
                       Kp + (size_t)(kv0_ + row_) * KLD + c_);                 \
            CP_ASYNC16(vbu[p_] + (uint32_t)(row_ * FVSTR + c_) * 4u,           \
                       Vp + (size_t)(kv0_ + row_) * KLD + c_);                 \
        }                                                                      \
        CP_COMMIT();                                                           \
    } while (0)

    LOAD_KV(0);
    LOAD_KV(1);

    float mrow0 = -1e30f, mrow1 = -1e30f;
    float lrow0 = 0.f, lrow1 = 0.f;
    float o[16][4];
#pragma unroll
    for (int i = 0; i < 16; i++)
#pragma unroll
        for (int j = 0; j < 4; j++) o[i][j] = 0.f;

    const int r0g = q0 + wm + g, r1g = r0g + 8;
    const int l1 = (lane & ~3) | (tg >> 1);
    const bool odd = (tg & 1) != 0;

    for (int t = 0; t < nkv; t++) {
        const int p = t & 1, kv0 = t * 64;
        if (t + 1 < nkv) { CP_WAIT(1); } else { CP_WAIT(0); }
        __syncthreads();

        float sacc[8][4];
#pragma unroll
        for (int nt = 0; nt < 8; nt++)
#pragma unroll
            for (int j = 0; j < 4; j++) sacc[nt][j] = 0.f;

        const uint32_t* kb = p ? kbuf1 : kbuf0;
#pragma unroll
        for (int ks = 0; ks < 16; ks++) {
#pragma unroll
            for (int nt = 0; nt < 8; nt++) {
                uint32_t bf[2];
                const uint32_t* bp = kb + (nt * 8 + g) * FKSTR + ks * 8 + tg;
                bf[0] = bp[0];
                bf[1] = bp[4];
                mma8(sacc[nt], qf[ks], bf);
            }
        }

        float mnew0 = mrow0, mnew1 = mrow1;
        const bool domask = (kv0 + 63 > q0);
#pragma unroll
        for (int nt = 0; nt < 8; nt++) {
            const int c0 = kv0 + nt * 8 + 2 * tg, c1 = c0 + 1;
            float v0 = sacc[nt][0], v1 = sacc[nt][1];
            float v2 = sacc[nt][2], v3 = sacc[nt][3];
            if (domask) {
                if (c0 > r0g) v0 = -1e30f;
                if (c1 > r0g) v1 = -1e30f;
                if (c0 > r1g) v2 = -1e30f;
                if (c1 > r1g) v3 = -1e30f;
            }
            sacc[nt][0] = v0; sacc[nt][1] = v1; sacc[nt][2] = v2; sacc[nt][3] = v3;
            mnew0 = fmaxf(mnew0, fmaxf(v0, v1));
            mnew1 = fmaxf(mnew1, fmaxf(v2, v3));
        }
        mnew0 = fmaxf(mnew0, __shfl_xor_sync(0xffffffffu, mnew0, 1));
        mnew0 = fmaxf(mnew0, __shfl_xor_sync(0xffffffffu, mnew0, 2));
        mnew1 = fmaxf(mnew1, __shfl_xor_sync(0xffffffffu, mnew1, 1));
        mnew1 = fmaxf(mnew1, __shfl_xor_sync(0xffffffffu, mnew1, 2));

        const float f0 = __expf(mrow0 - mnew0);
        const float f1 = __expf(mrow1 - mnew1);

        float rs0 = 0.f, rs1 = 0.f;
#pragma unroll
        for (int nt = 0; nt < 8; nt++) {
            const float e0 = __expf(sacc[nt][0] - mnew0);
            const float e1 = __expf(sacc[nt][1] - mnew0);
            const float e2 = __expf(sacc[nt][2] - mnew1);
            const float e3 = __expf(sacc[nt][3] - mnew1);
            sacc[nt][0] = e0; sacc[nt][1] = e1; sacc[nt][2] = e2; sacc[nt][3] = e3;
            rs0 += e0 + e1;
            rs1 += e2 + e3;
        }
        rs0 += __shfl_xor_sync(0xffffffffu, rs0, 1);
        rs0 += __shfl_xor_sync(0xffffffffu, rs0, 2);
        rs1 += __shfl_xor_sync(0xffffffffu, rs1, 1);
        rs1 += __shfl_xor_sync(0xffffffffu, rs1, 2);

        lrow0 = lrow0 * f0 + rs0;
        lrow1 = lrow1 * f1 + rs1;
        mrow0 = mnew0;
        mrow1 = mnew1;

#pragma unroll
        for (int nt2 = 0; nt2 < 16; nt2++) {
            o[nt2][0] *= f0; o[nt2][1] *= f0;
            o[nt2][2] *= f1; o[nt2][3] *= f1;
        }

        const uint32_t* vb_ = p ? vbuf1 : vbuf0;
#pragma unroll
        for (int ks2 = 0; ks2 < 8; ks2++) {
            const float c0 = sacc[ks2][0], c1 = sacc[ks2][1];
            const float c2 = sacc[ks2][2], c3 = sacc[ks2][3];
            const float v00 = __shfl_sync(0xffffffffu, c0, l1);
            const float v01 = __shfl_sync(0xffffffffu, c1, l1);
            const float v10 = __shfl_sync(0xffffffffu, c2, l1);
            const float v11 = __shfl_sync(0xffffffffu, c3, l1);
            const float w00 = __shfl_sync(0xffffffffu, c0, l1 + 2);
            const float w01 = __shfl_sync(0xffffffffu, c1, l1 + 2);
            const float w10 = __shfl_sync(0xffffffffu, c2, l1 + 2);
            const float w11 = __shfl_sync(0xffffffffu, c3, l1 + 2);
            uint32_t pa[4];
            pa[0] = f2tf(odd ? v01 : v00);
            pa[1] = f2tf(odd ? v11 : v10);
            pa[2] = f2tf(odd ? w01 : w00);
            pa[3] = f2tf(odd ? w11 : w10);
#pragma unroll
            for (int nt2 = 0; nt2 < 16; nt2++) {
                uint32_t bf[2];
                const uint32_t* bp = vb_ + (ks2 * 8 + tg) * FVSTR + nt2 * 8 + g;
                bf[0] = bp[0];
                bf[1] = bp[4 * FVSTR];
                mma8(o[nt2], pa, bf);
            }
        }

        __syncthreads();
        if (t + 2 < nkv) LOAD_KV(t + 2);
    }

    const float inv0 = 1.f / lrow0;
    const float inv1 = 1.f / lrow1;
    float* orow0 = g_attn + (size_t)(b * SEQ + r0g) * QLD + h * HD;
    float* orow1 = g_attn + (size_t)(b * SEQ + r1g) * QLD + h * HD;
#pragma unroll
    for (int nt2 = 0; nt2 < 16; nt2++) {
        const int c = nt2 * 8 + 2 * tg;
        *(float2*)(orow0 + c) = make_float2(round_tf(o[nt2][0] * inv0),
                                            round_tf(o[nt2][1] * inv0));
        *(float2*)(orow1 + c) = make_float2(round_tf(o[nt2][2] * inv1),
                                            round_tf(o[nt2][3] * inv1));
    }
#undef LOAD_KV
}

// ---------------- tf32 rounding prepass (MLP=4, exact coverage) --------------
__global__ void round_copy4(float4* __restrict__ dst, const float4* __restrict__ src) {
    const size_t base = (size_t)blockIdx.x * 1024 + threadIdx.x;
    float4 a = src[base];
    float4 b = src[base + 256];
    float4 c = src[base + 512];
    float4 d = src[base + 768];
    a.x = round_tf(a.x); a.y = round_tf(a.y); a.z = round_tf(a.z); a.w = round_tf(a.w);
    b.x = round_tf(b.x); b.y = round_tf(b.y); b.z = round_tf(b.z); b.w = round_tf(b.w);
    c.x = round_tf(c.x); c.y = round_tf(c.y); c.z = round_tf(c.z); c.w = round_tf(c.w);
    d.x = round_tf(d.x); d.y = round_tf(d.y); d.z = round_tf(d.z); d.w = round_tf(d.w);
    dst[base]       = a;
    dst[base + 256] = b;
    dst[base + 512] = c;
    dst[base + 768] = d;
}

// ---------------- RoPE (writes tf32-rounded; q also scaled by 1/sqrt(HD)) -----
__global__ void rope_q(const float* __restrict__ cosT, const float* __restrict__ sinT) {
    const int row = blockIdx.x;
    const int s = row & (SEQ - 1);
    const float sc = 0.08838834764831845f;   // 1/sqrt(128)
    const float* cr = cosT + (size_t)s * HD;
    const float* sr = sinT + (size_t)s * HD;
    float* base = g_q + (size_t)row * QLD;
    for (int idx = threadIdx.x; idx < NH * 64; idx += blockDim.x) {
        const int hh = idx >> 6, d = idx & 63;
        float* p = base + hh * HD;
        const float x1 = p[d], x2 = p[d + 64];
        p[d]      = round_tf((x1 * cr[d]      - x2 * sr[d])      * sc);
        p[d + 64] = round_tf((x2 * cr[d + 64] + x1 * sr[d + 64]) * sc);
    }
}
__global__ void rope_k(const float* __restrict__ cosT, const float* __restrict__ sinT) {
    const int row = blockIdx.x;
    const int s = row & (SEQ - 1);
    const float* cr = cosT + (size_t)s * HD;
    const float* sr = sinT + (size_t)s * HD;
    float* base = g_k + (size_t)row * KLD;
    for (int idx = threadIdx.x; idx < NKV * 64; idx += blockDim.x) {
        const int hh = idx >> 6, d = idx & 63;
        float* p = base + hh * HD;
        const float x1 = p[d], x2 = p[d + 64];
        p[d]      = round_tf(x1 * cr[d]      - x2 * sr[d]);
        p[d + 64] = round_tf(x2 * cr[d + 64] + x1 * sr[d + 64]);
    }
}

// ---------------- launch -----------------------------------------------------
extern "C" void kernel_launch(void* const* d_in, const int* in_sizes, int n_in,
                              void* d_out, int out_size) {
    (void)in_sizes; (void)n_in; (void)out_size;
    const float* hs   = (const float*)d_in[0];
    const float* Wq   = (const float*)d_in[1];
    const float* Wk   = (const float*)d_in[2];
    const float* Wv   = (const float*)d_in[3];
    const float* Wo   = (const float*)d_in[4];
    const float* cosT = (const float*)d_in[5];
    const float* sinT = (const float*)d_in[6];
    float* out = (float*)d_out;

    static bool attr_set = false;
    if (!attr_set) {
        cudaFuncSetAttribute(k_proj_qkv, cudaFuncAttributeMaxDynamicSharedMemorySize, PSMEM);
        cudaFuncSetAttribute(k_out_proj, cudaFuncAttributeMaxDynamicSharedMemorySize, PSMEM);
        cudaFuncSetAttribute(k_flash,    cudaFuncAttributeMaxDynamicSharedMemorySize, FSMEM);
        attr_set = true;
    }

    float* phs;  cudaGetSymbolAddress((void**)&phs, g_hs);
    float* pwq;  cudaGetSymbolAddress((void**)&pwq, g_wq);
    float* pwk;  cudaGetSymbolAddress((void**)&pwk, g_wk);
    float* pwv;  cudaGetSymbolAddress((void**)&pwv, g_wv);
    float* pwo;  cudaGetSymbolAddress((void**)&pwo, g_wo);

    round_copy4<<<((size_t)ROWS * HDIM / 4) / 1024, 256>>>((float4*)phs, (const float4*)hs);
    round_copy4<<<((size_t)QLD * HDIM / 4) / 1024, 256>>>((float4*)pwq, (const float4*)Wq);
    round_copy4<<<((size_t)KLD * HDIM / 4) / 1024, 256>>>((float4*)pwk, (const float4*)Wk);
    round_copy4<<<((size_t)KLD * HDIM / 4) / 1024, 256>>>((float4*)pwv, (const float4*)Wv);
    round_copy4<<<((size_t)HDIM * QLD / 4) / 1024, 256>>>((float4*)pwo, (const float4*)Wo);

    k_proj_qkv<<<dim3(48, ROWS / 128), 128, PSMEM>>>();
    rope_q<<<ROWS, 256>>>(cosT, sinT);
    rope_k<<<ROWS, 256>>>(cosT, sinT);
    k_flash<<<dim3(SEQ / 128, NBH), 256, FSMEM>>>();
    k_out_proj<<<dim3(HDIM / 128, ROWS / 128), 128, PSMEM>>>(out);
}

// round 8
// speedup vs baseline: 1.9132x; 1.4698x over previous
#include <cuda_runtime.h>
#include <cuda_fp16.h>
#include <cstdint>

#define SEQ 2048
#define NB 2
#define ROWS (NB * SEQ)      // 4096 total (b,s) rows
#define HDIM 4096
#define NH 32
#define NKV 8
#define HD 128
#define QLD (NH * HD)        // 4096
#define KLD (NKV * HD)       // 1024
#define NBH (NB * NH)        // 64

// ---------------- scratch (static device allocations; no cudaMalloc) -------
__device__ float g_q[(size_t)ROWS * QLD];                 // 64 MB (fp32, tf32 bits after rope)
__device__ float g_k[(size_t)ROWS * KLD];                 // 16 MB
__device__ float g_v[(size_t)ROWS * KLD];                 // 16 MB
// fp16 operands for the projection-class GEMMs
__device__ __half g_hs16[(size_t)ROWS * HDIM];            // 32 MB
__device__ __half g_wq16[(size_t)QLD * HDIM];             // 32 MB
__device__ __half g_wk16[(size_t)KLD * HDIM];             // 8 MB
__device__ __half g_wv16[(size_t)KLD * HDIM];             // 8 MB
__device__ __half g_wo16[(size_t)HDIM * QLD];             // 32 MB
__device__ __half g_attn16[(size_t)ROWS * QLD];           // 32 MB (flash output)

// ---------------- helpers ---------------------------------------------------
__device__ __forceinline__ uint32_t smem_u32(const void* p) {
    uint32_t a;
    asm("{ .reg .u64 t; cvta.to.shared.u64 t, %1; cvt.u32.u64 %0, t; }" : "=r"(a) : "l"(p));
    return a;
}
__device__ __forceinline__ uint32_t f2tf(float f) {
    uint32_t u;
    asm("cvt.rna.tf32.f32 %0, %1;" : "=r"(u) : "f"(f));
    return u;
}
__device__ __forceinline__ float round_tf(float f) {
    return __uint_as_float(f2tf(f));
}

#define CP_ASYNC16(dst, src) \
    asm volatile("cp.async.cg.shared.global [%0], [%1], 16;" :: "r"(dst), "l"(src) : "memory")
#define CP_COMMIT() asm volatile("cp.async.commit_group;" ::: "memory")
#define CP_WAIT(n)  asm volatile("cp.async.wait_group %0;" :: "n"(n) : "memory")

// tf32 mma (flash path)
__device__ __forceinline__ void mma8(float* c, const uint32_t* a, const uint32_t* b) {
    asm volatile(
        "mma.sync.aligned.m16n8k8.row.col.f32.tf32.tf32.f32 "
        "{%0,%1,%2,%3}, {%4,%5,%6,%7}, {%8,%9}, {%0,%1,%2,%3};\n"
        : "+f"(c[0]), "+f"(c[1]), "+f"(c[2]), "+f"(c[3])
        : "r"(a[0]), "r"(a[1]), "r"(a[2]), "r"(a[3]), "r"(b[0]), "r"(b[1]));
}
// fp16 mma (projection path): 16x8x16, fp32 accumulate
__device__ __forceinline__ void mma16(float* c, const uint32_t* a, const uint32_t* b) {
    asm volatile(
        "mma.sync.aligned.m16n8k16.row.col.f32.f16.f16.f32 "
        "{%0,%1,%2,%3}, {%4,%5,%6,%7}, {%8,%9}, {%0,%1,%2,%3};\n"
        : "+f"(c[0]), "+f"(c[1]), "+f"(c[2]), "+f"(c[3])
        : "r"(a[0]), "r"(a[1]), "r"(a[2]), "r"(a[3]), "r"(b[0]), "r"(b[1]));
}

// ============================================================================
// Projection GEMM (fp16 operands, fp32 out): C[128,128] tile = A * B^T.
// A [M,K], B [N,K] row-major __half.  128 threads = 4 warps (2m x 2n),
// warp tile 64x64.  BK=32 halves (64B rows), 4-stage cp.async, 2 CTAs/SM.
// smem rows stride 40 halves (20 words) -> conflict-free fragment loads.
// ============================================================================
#define HBK 32
#define HSTAGE 4
#define HSTR 40                                // halves
#define HSTRW 20                               // words
#define HT_BYTES (128 * HSTR * 2)              // 10240 per tile
#define HSTAGE_BYTES (2 * HT_BYTES)            // 20480
#define PSMEM_H (HSTAGE * HSTAGE_BYTES)        // 81920

__device__ __noinline__ void pgemm_h(
    const __half* __restrict__ A, const __half* __restrict__ B, float* __restrict__ C,
    int m0, int n0, int K, int lda, int ldb, int ldc, bool rnd)
{
    extern __shared__ float dsm[];
    const uint32_t sbase = smem_u32(dsm);

    const int tid = threadIdx.x;
    const int arow = tid >> 2;          // 0..31 (rows arow + 32*i)
    const int ac = (tid & 3) << 3;      // half offset within row: 0,8,16,24

    const int warp = tid >> 5;
    const int lane = tid & 31;
    const int wm = (warp & 1) << 6;     // 0,64
    const int wn = (warp >> 1) << 6;    // 0,64
    const int g  = lane >> 2;
    const int tg = lane & 3;

    float acc[4][8][4];
#pragma unroll
    for (int i = 0; i < 4; i++)
#pragma unroll
        for (int j = 0; j < 8; j++)
#pragma unroll
            for (int l = 0; l < 4; l++) acc[i][j][l] = 0.f;

    const int nk = K / HBK;

#define HLOAD(s) do {                                                              \
        const uint32_t sa_u = sbase + (uint32_t)((s) & (HSTAGE - 1)) * HSTAGE_BYTES; \
        const uint32_t sb_u = sa_u + HT_BYTES;                                     \
        const __half* pa_ = A + (size_t)(m0 + arow) * lda + (s) * HBK + ac;        \
        const __half* pb_ = B + (size_t)(n0 + arow) * ldb + (s) * HBK + ac;        \
        _Pragma("unroll")                                                          \
        for (int r_ = 0; r_ < 128; r_ += 32) {                                     \
            CP_ASYNC16(sa_u + (uint32_t)((arow + r_) * HSTR + ac) * 2u,            \
                       pa_ + (size_t)r_ * lda);                                    \
            CP_ASYNC16(sb_u + (uint32_t)((arow + r_) * HSTR + ac) * 2u,            \
                       pb_ + (size_t)r_ * ldb);                                    \
        }                                                                          \
    } while (0)

#pragma unroll
    for (int s = 0; s < HSTAGE - 1; s++) {
        if (s < nk) HLOAD(s);
        CP_COMMIT();
    }

    for (int kt = 0; kt < nk; kt++) {
        CP_WAIT(HSTAGE - 2);
        __syncthreads();
        if (kt + HSTAGE - 1 < nk) HLOAD(kt + HSTAGE - 1);
        CP_COMMIT();

        const uint32_t* sa = (const uint32_t*)dsm + (size_t)(kt & (HSTAGE - 1)) * (HSTAGE_BYTES / 4);
        const uint32_t* sb = sa + HT_BYTES / 4;

#pragma unroll
        for (int ks = 0; ks < 2; ks++) {       // two k16 steps per 32-k tile
            const int kb = ks * 8;             // word offset
            uint32_t af[4][4];
#pragma unroll
            for (int mt = 0; mt < 4; mt++) {
                const uint32_t* base = &sa[(wm + mt * 16 + g) * HSTRW + kb + tg];
                af[mt][0] = base[0];               // row g,   k 2tg..2tg+1
                af[mt][1] = base[8 * HSTRW];       // row g+8, k 2tg..2tg+1
                af[mt][2] = base[4];               // row g,   k 2tg+8..+9
                af[mt][3] = base[8 * HSTRW + 4];   // row g+8, k 2tg+8..+9
            }
            uint32_t bf[8][2];
#pragma unroll
            for (int nt = 0; nt < 8; nt++) {
                const uint32_t* base = &sb[(wn + nt * 8 + g) * HSTRW + kb + tg];
                bf[nt][0] = base[0];               // n g, k 2tg..2tg+1
                bf[nt][1] = base[4];               // n g, k 2tg+8..+9
            }
#pragma unroll
            for (int mt = 0; mt < 4; mt++)
#pragma unroll
                for (int nt = 0; nt < 8; nt++)
                    mma16(acc[mt][nt], af[mt], bf[nt]);
        }
        __syncthreads();
    }

#pragma unroll
    for (int mt = 0; mt < 4; mt++) {
        const int r = m0 + wm + mt * 16 + g;
#pragma unroll
        for (int nt = 0; nt < 8; nt++) {
            const int c = n0 + wn + nt * 8 + (tg << 1);
            float v0 = acc[mt][nt][0], v1 = acc[mt][nt][1];
            float v2 = acc[mt][nt][2], v3 = acc[mt][nt][3];
            if (rnd) {
                v0 = round_tf(v0); v1 = round_tf(v1);
                v2 = round_tf(v2); v3 = round_tf(v3);
            }
            float* p0 = C + (size_t)r * ldc + c;
            *(float2*)p0 = make_float2(v0, v1);
            float* p1 = p0 + (size_t)8 * ldc;
            *(float2*)p1 = make_float2(v2, v3);
        }
    }
#undef HLOAD
}

// ---------------- projection wrappers ----------------------------------------
// merged QKV: grid (48, 32); x: [0,32)->Q, [32,40)->K, [40,48)->V (V rounds tf32)
__global__ void __launch_bounds__(128, 2) k_proj_qkv() {
    const int nb = blockIdx.x;
    const int m0 = blockIdx.y * 128;
    if (nb < 32) {
        pgemm_h(g_hs16, g_wq16, g_q, m0, nb * 128, HDIM, HDIM, HDIM, QLD, false);
    } else if (nb < 40) {
        pgemm_h(g_hs16, g_wk16, g_k, m0, (nb - 32) * 128, HDIM, HDIM, HDIM, KLD, false);
    } else {
        pgemm_h(g_hs16, g_wv16, g_v, m0, (nb - 40) * 128, HDIM, HDIM, HDIM, KLD, true);
    }
}
__global__ void __launch_bounds__(128, 2) k_out_proj(float* __restrict__ out) {
    pgemm_h(g_attn16, g_wo16, out, blockIdx.y * 128, blockIdx.x * 128, QLD, QLD, HDIM, HDIM, false);
}

// ============================================================================
// Fused flash attention (causal, online softmax), tf32 mma.
// Grid (16 q-blocks [reversed], 64 z).  256 threads = 8 warps, 16 Q rows each.
// Q is pre-scaled by 1/sqrt(HD) in rope_q.  Output -> g_attn16 (fp16).
// ============================================================================
#define FKSTR 132
#define FVSTR 136
#define FK_U32 (64 * FKSTR)       // 8448
#define FV_U32 (64 * FVSTR)       // 8704
#define FSMEM ((2 * FK_U32 + 2 * FV_U32) * 4)   // 137216 bytes

__global__ void __launch_bounds__(256, 1) k_flash() {
    extern __shared__ uint32_t fsm[];
    const uint32_t sbase = smem_u32(fsm);

    const int tid = threadIdx.x;
    const int wid = tid >> 5, lane = tid & 31;
    const int g = lane >> 2, tg = lane & 3;
    const int wm = wid * 16;

    const int z = blockIdx.y, b = z >> 5, h = z & 31, kvh = h >> 2;
    const int qb = (int)(gridDim.x - 1 - blockIdx.x);
    const int q0 = qb * 128;
    const int nkv = 2 * qb + 2;

    const float* Qp = g_q + (size_t)(b * SEQ + q0) * QLD + h * HD;
    const float* Kp = g_k + (size_t)b * SEQ * KLD + kvh * HD;
    const float* Vp = g_v + (size_t)b * SEQ * KLD + kvh * HD;

#pragma unroll
    for (int i = 0; i < 16; i++) {
        const int op = tid + i * 256;
        const int row = op >> 5, c = (op & 31) << 2;
        CP_ASYNC16(sbase + (uint32_t)(row * FKSTR + c) * 4u, Qp + (size_t)row * QLD + c);
    }
    CP_COMMIT();
    CP_WAIT(0);
    __syncthreads();

    uint32_t qf[16][4];
#pragma unroll
    for (int ks = 0; ks < 16; ks++) {
        const uint32_t* bp = fsm + (wm + g) * FKSTR + ks * 8 + tg;
        qf[ks][0] = bp[0];
        qf[ks][1] = bp[8 * FKSTR];
        qf[ks][2] = bp[4];
        qf[ks][3] = bp[8 * FKSTR + 4];
    }
    __syncthreads();

    const uint32_t* kbuf0 = fsm;
    const uint32_t* kbuf1 = fsm + FK_U32;
    const uint32_t* vbuf0 = fsm + 2 * FK_U32;
    const uint32_t* vbuf1 = vbuf0 + FV_U32;
    const uint32_t kbu[2] = { sbase, sbase + FK_U32 * 4u };
    const uint32_t vbu[2] = { sbase + 2u * FK_U32 * 4u, sbase + 2u * FK_U32 * 4u + FV_U32 * 4u };

#define LOAD_KV(t) do {                                                        \
        const int kv0_ = (t) * 64, p_ = (t) & 1;                               \
        _Pragma("unroll")                                                      \
        for (int i_ = 0; i_ < 8; i_++) {                                       \
            const int op_ = tid + i_ * 256;                                    \
            const int row_ = op_ >> 5, c_ = (op_ & 31) << 2;                   \
            CP_ASYNC16(kbu[p_] + (uint32_t)(row_ * FKSTR + c_) * 4u,           \
                       Kp + (size_t)(kv0_ + row_) * KLD + c_);                 \
            CP_ASYNC16(vbu[p_] + (uint32_t)(row_ * FVSTR + c_) * 4u,           \
                       Vp + (size_t)(kv0_ + row_) * KLD + c_);                 \
        }                                                                      \
        CP_COMMIT();                                                           \
    } while (0)

    LOAD_KV(0);
    LOAD_KV(1);

    float mrow0 = -1e30f, mrow1 = -1e30f;
    float lrow0 = 0.f, lrow1 = 0.f;
    float o[16][4];
#pragma unroll
    for (int i = 0; i < 16; i++)
#pragma unroll
        for (int j = 0; j < 4; j++) o[i][j] = 0.f;

    const int r0g = q0 + wm + g, r1g = r0g + 8;
    const int l1 = (lane & ~3) | (tg >> 1);
    const bool odd = (tg & 1) != 0;

    for (int t = 0; t < nkv; t++) {
        const int p = t & 1, kv0 = t * 64;
        if (t + 1 < nkv) { CP_WAIT(1); } else { CP_WAIT(0); }
        __syncthreads();

        float sacc[8][4];
#pragma unroll
        for (int nt = 0; nt < 8; nt++)
#pragma unroll
            for (int j = 0; j < 4; j++) sacc[nt][j] = 0.f;

        const uint32_t* kb = p ? kbuf1 : kbuf0;
#pragma unroll
        for (int ks = 0; ks < 16; ks++) {
#pragma unroll
            for (int nt = 0; nt < 8; nt++) {
                uint32_t bf[2];
                const uint32_t* bp = kb + (nt * 8 + g) * FKSTR + ks * 8 + tg;
                bf[0] = bp[0];
                bf[1] = bp[4];
                mma8(sacc[nt], qf[ks], bf);
            }
        }

        float mnew0 = mrow0, mnew1 = mrow1;
        const bool domask = (kv0 + 63 > q0);
#pragma unroll
        for (int nt = 0; nt < 8; nt++) {
            const int c0 = kv0 + nt * 8 + 2 * tg, c1 = c0 + 1;
            float v0 = sacc[nt][0], v1 = sacc[nt][1];
            float v2 = sacc[nt][2], v3 = sacc[nt][3];
            if (domask) {
                if (c0 > r0g) v0 = -1e30f;
                if (c1 > r0g) v1 = -1e30f;
                if (c0 > r1g) v2 = -1e30f;
                if (c1 > r1g) v3 = -1e30f;
            }
            sacc[nt][0] = v0; sacc[nt][1] = v1; sacc[nt][2] = v2; sacc[nt][3] = v3;
            mnew0 = fmaxf(mnew0, fmaxf(v0, v1));
            mnew1 = fmaxf(mnew1, fmaxf(v2, v3));
        }
        mnew0 = fmaxf(mnew0, __shfl_xor_sync(0xffffffffu, mnew0, 1));
        mnew0 = fmaxf(mnew0, __shfl_xor_sync(0xffffffffu, mnew0, 2));
        mnew1 = fmaxf(mnew1, __shfl_xor_sync(0xffffffffu, mnew1, 1));
        mnew1 = fmaxf(mnew1, __shfl_xor_sync(0xffffffffu, mnew1, 2));

        const float f0 = __expf(mrow0 - mnew0);
        const float f1 = __expf(mrow1 - mnew1);

        float rs0 = 0.f, rs1 = 0.f;
#pragma unroll
        for (int nt = 0; nt < 8; nt++) {
            const float e0 = __expf(sacc[nt][0] - mnew0);
            const float e1 = __expf(sacc[nt][1] - mnew0);
            const float e2 = __expf(sacc[nt][2] - mnew1);
            const float e3 = __expf(sacc[nt][3] - mnew1);
            sacc[nt][0] = e0; sacc[nt][1] = e1; sacc[nt][2] = e2; sacc[nt][3] = e3;
            rs0 += e0 + e1;
            rs1 += e2 + e3;
        }
        rs0 += __shfl_xor_sync(0xffffffffu, rs0, 1);
        rs0 += __shfl_xor_sync(0xffffffffu, rs0, 2);
        rs1 += __shfl_xor_sync(0xffffffffu, rs1, 1);
        rs1 += __shfl_xor_sync(0xffffffffu, rs1, 2);

        lrow0 = lrow0 * f0 + rs0;
        lrow1 = lrow1 * f1 + rs1;
        mrow0 = mnew0;
        mrow1 = mnew1;

#pragma unroll
        for (int nt2 = 0; nt2 < 16; nt2++) {
            o[nt2][0] *= f0; o[nt2][1] *= f0;
            o[nt2][2] *= f1; o[nt2][3] *= f1;
        }

        const uint32_t* vb_ = p ? vbuf1 : vbuf0;
#pragma unroll
        for (int ks2 = 0; ks2 < 8; ks2++) {
            const float c0 = sacc[ks2][0], c1 = sacc[ks2][1];
            const float c2 = sacc[ks2][2], c3 = sacc[ks2][3];
            const float v00 = __shfl_sync(0xffffffffu, c0, l1);
            const float v01 = __shfl_sync(0xffffffffu, c1, l1);
            const float v10 = __shfl_sync(0xffffffffu, c2, l1);
            const float v11 = __shfl_sync(0xffffffffu, c3, l1);
            const float w00 = __shfl_sync(0xffffffffu, c0, l1 + 2);
            const float w01 = __shfl_sync(0xffffffffu, c1, l1 + 2);
            const float w10 = __shfl_sync(0xffffffffu, c2, l1 + 2);
            const float w11 = __shfl_sync(0xffffffffu, c3, l1 + 2);
            uint32_t pa[4];
            pa[0] = f2tf(odd ? v01 : v00);
            pa[1] = f2tf(odd ? v11 : v10);
            pa[2] = f2tf(odd ? w01 : w00);
            pa[3] = f2tf(odd ? w11 : w10);
#pragma unroll
            for (int nt2 = 0; nt2 < 16; nt2++) {
                uint32_t bf[2];
                const uint32_t* bp = vb_ + (ks2 * 8 + tg) * FVSTR + nt2 * 8 + g;
                bf[0] = bp[0];
                bf[1] = bp[4 * FVSTR];
                mma8(o[nt2], pa, bf);
            }
        }

        __syncthreads();
        if (t + 2 < nkv) LOAD_KV(t + 2);
    }

    // epilogue: normalize, convert to fp16 (feeds out_proj A operand)
    const float inv0 = 1.f / lrow0;
    const float inv1 = 1.f / lrow1;
    __half* orow0 = g_attn16 + (size_t)(b * SEQ + r0g) * QLD + h * HD;
    __half* orow1 = g_attn16 + (size_t)(b * SEQ + r1g) * QLD + h * HD;
#pragma unroll
    for (int nt2 = 0; nt2 < 16; nt2++) {
        const int c = nt2 * 8 + 2 * tg;
        *(__half2*)(orow0 + c) = __floats2half2_rn(o[nt2][0] * inv0, o[nt2][1] * inv0);
        *(__half2*)(orow1 + c) = __floats2half2_rn(o[nt2][2] * inv1, o[nt2][3] * inv1);
    }
#undef LOAD_KV
}

// ---------------- fp32 -> fp16 prepass (MLP=4) --------------------------------
// grid = n_floats / 8192, block 256; each thread: 4 outputs of 8 halves.
__global__ void cvt_half4(uint4* __restrict__ dst, const float4* __restrict__ src) {
    const size_t base = (size_t)blockIdx.x * 1024 + threadIdx.x;
#pragma unroll
    for (int i = 0; i < 4; i++) {
        const size_t oi = base + i * 256;
        const float4 a = src[2 * oi];
        const float4 b = src[2 * oi + 1];
        __half2 h0 = __floats2half2_rn(a.x, a.y);
        __half2 h1 = __floats2half2_rn(a.z, a.w);
        __half2 h2 = __floats2half2_rn(b.x, b.y);
        __half2 h3 = __floats2half2_rn(b.z, b.w);
        uint4 o4;
        o4.x = *(uint32_t*)&h0;
        o4.y = *(uint32_t*)&h1;
        o4.z = *(uint32_t*)&h2;
        o4.w = *(uint32_t*)&h3;
        dst[oi] = o4;
    }
}

// ---------------- RoPE (writes tf32-rounded; q also scaled by 1/sqrt(HD)) -----
__global__ void rope_q(const float* __restrict__ cosT, const float* __restrict__ sinT) {
    const int row = blockIdx.x;
    const int s = row & (SEQ - 1);
    const float sc = 0.08838834764831845f;   // 1/sqrt(128)
    const float* cr = cosT + (size_t)s * HD;
    const float* sr = sinT + (size_t)s * HD;
    float* base = g_q + (size_t)row * QLD;
    for (int idx = threadIdx.x; idx < NH * 64; idx += blockDim.x) {
        const int hh = idx >> 6, d = idx & 63;
        float* p = base + hh * HD;
        const float x1 = p[d], x2 = p[d + 64];
        p[d]      = round_tf((x1 * cr[d]      - x2 * sr[d])      * sc);
        p[d + 64] = round_tf((x2 * cr[d + 64] + x1 * sr[d + 64]) * sc);
    }
}
__global__ void rope_k(const float* __restrict__ cosT, const float* __restrict__ sinT) {
    const int row = blockIdx.x;
    const int s = row & (SEQ - 1);
    const float* cr = cosT + (size_t)s * HD;
    const float* sr = sinT + (size_t)s * HD;
    float* base = g_k + (size_t)row * KLD;
    for (int idx = threadIdx.x; idx < NKV * 64; idx += blockDim.x) {
        const int hh = idx >> 6, d = idx & 63;
        float* p = base + hh * HD;
        const float x1 = p[d], x2 = p[d + 64];
        p[d]      = round_tf(x1 * cr[d]      - x2 * sr[d]);
        p[d + 64] = round_tf(x2 * cr[d + 64] + x1 * sr[d + 64]);
    }
}

// ---------------- launch -----------------------------------------------------
extern "C" void kernel_launch(void* const* d_in, const int* in_sizes, int n_in,
                              void* d_out, int out_size) {
    (void)in_sizes; (void)n_in; (void)out_size;
    const float* hs   = (const float*)d_in[0];
    const float* Wq   = (const float*)d_in[1];
    const float* Wk   = (const float*)d_in[2];
    const float* Wv   = (const float*)d_in[3];
    const float* Wo   = (const float*)d_in[4];
    const float* cosT = (const float*)d_in[5];
    const float* sinT = (const float*)d_in[6];
    float* out = (float*)d_out;

    static bool attr_set = false;
    if (!attr_set) {
        cudaFuncSetAttribute(k_proj_qkv, cudaFuncAttributeMaxDynamicSharedMemorySize, PSMEM_H);
        cudaFuncSetAttribute(k_out_proj, cudaFuncAttributeMaxDynamicSharedMemorySize, PSMEM_H);
        cudaFuncSetAttribute(k_flash,    cudaFuncAttributeMaxDynamicSharedMemorySize, FSMEM);
        attr_set = true;
    }

    void* phs;  cudaGetSymbolAddress(&phs, g_hs16);
    void* pwq;  cudaGetSymbolAddress(&pwq, g_wq16);
    void* pwk;  cudaGetSymbolAddress(&pwk, g_wk16);
    void* pwv;  cudaGetSymbolAddress(&pwv, g_wv16);
    void* pwo;  cudaGetSymbolAddress(&pwo, g_wo16);

    // grid = n_floats / 8192 (all sizes divide exactly)
    cvt_half4<<<((size_t)ROWS * HDIM) / 8192, 256>>>((uint4*)phs, (const float4*)hs);
    cvt_half4<<<((size_t)QLD * HDIM) / 8192, 256>>>((uint4*)pwq, (const float4*)Wq);
    cvt_half4<<<((size_t)KLD * HDIM) / 8192, 256>>>((uint4*)pwk, (const float4*)Wk);
    cvt_half4<<<((size_t)KLD * HDIM) / 8192, 256>>>((uint4*)pwv, (const float4*)Wv);
    cvt_half4<<<((size_t)HDIM * QLD) / 8192, 256>>>((uint4*)pwo, (const float4*)Wo);

    k_proj_qkv<<<dim3(48, ROWS / 128), 128, PSMEM_H>>>();
    rope_q<<<ROWS, 256>>>(cosT, sinT);
    rope_k<<<ROWS, 256>>>(cosT, sinT);
    k_flash<<<dim3(SEQ / 128, NBH), 256, FSMEM>>>();
    k_out_proj<<<dim3(HDIM / 128, ROWS / 128), 128, PSMEM_H>>>(out);
}

// round 9
// speedup vs baseline: 2.0762x; 1.0852x over previous
#include <cuda_runtime.h>
#include <cuda_fp16.h>
#include <cstdint>

#define SEQ 2048
#define NB 2
#define ROWS (NB * SEQ)      // 4096 total (b,s) rows
#define HDIM 4096
#define NH 32
#define NKV 8
#define HD 128
#define QLD (NH * HD)        // 4096
#define KLD (NKV * HD)       // 1024
#define NBH (NB * NH)        // 64

// ---------------- scratch (static device allocations; no cudaMalloc) -------
__device__ float g_q[(size_t)ROWS * QLD];                 // 64 MB (fp32 proj out)
__device__ float g_k[(size_t)ROWS * KLD];                 // 16 MB (fp32 proj out)
// fp16 operands
__device__ __half g_hs16[(size_t)ROWS * HDIM];            // 32 MB
__device__ __half g_wq16[(size_t)QLD * HDIM];             // 32 MB
__device__ __half g_wk16[(size_t)KLD * HDIM];             // 8 MB
__device__ __half g_wv16[(size_t)KLD * HDIM];             // 8 MB
__device__ __half g_wo16[(size_t)HDIM * QLD];             // 32 MB
__device__ __half g_q16[(size_t)ROWS * QLD];              // 32 MB (rope out, scaled)
__device__ __half g_k16[(size_t)ROWS * KLD];              // 8 MB  (rope out)
__device__ __half g_v16t[(size_t)NB * KLD * SEQ];         // 8 MB  (V transposed [b][kv][d][s])
__device__ __half g_attn16[(size_t)ROWS * QLD];           // 32 MB (flash out)

// ---------------- helpers ---------------------------------------------------
__device__ __forceinline__ uint32_t smem_u32(const void* p) {
    uint32_t a;
    asm("{ .reg .u64 t; cvta.to.shared.u64 t, %1; cvt.u32.u64 %0, t; }" : "=r"(a) : "l"(p));
    return a;
}
__device__ __forceinline__ uint32_t packh2(float a, float b) {
    __half2 h = __floats2half2_rn(a, b);
    return *(uint32_t*)&h;
}

#define CP_ASYNC16(dst, src) \
    asm volatile("cp.async.cg.shared.global [%0], [%1], 16;" :: "r"(dst), "l"(src) : "memory")
#define CP_COMMIT() asm volatile("cp.async.commit_group;" ::: "memory")
#define CP_WAIT(n)  asm volatile("cp.async.wait_group %0;" :: "n"(n) : "memory")

// fp16 mma: 16x8x16, fp32 accumulate
__device__ __forceinline__ void mma16(float* c, const uint32_t* a, const uint32_t* b) {
    asm volatile(
        "mma.sync.aligned.m16n8k16.row.col.f32.f16.f16.f32 "
        "{%0,%1,%2,%3}, {%4,%5,%6,%7}, {%8,%9}, {%0,%1,%2,%3};\n"
        : "+f"(c[0]), "+f"(c[1]), "+f"(c[2]), "+f"(c[3])
        : "r"(a[0]), "r"(a[1]), "r"(a[2]), "r"(a[3]), "r"(b[0]), "r"(b[1]));
}

// ============================================================================
// Projection GEMM (fp16 operands): C[128,128] tile = A * B^T.
// A [M,K], B [N,K] row-major __half.  128 threads = 4 warps (2m x 2n),
// warp tile 64x64.  BK=32 halves, 4-stage cp.async, 2 CTAs/SM.
// MODE 0: fp32 C out.  MODE 1: V-transposed fp16 out -> g_v16t.
// ============================================================================
#define HBK 32
#define HSTAGE 4
#define HSTR 40                                // halves
#define HSTRW 20                               // words
#define HT_BYTES (128 * HSTR * 2)              // 10240 per tile
#define HSTAGE_BYTES (2 * HT_BYTES)            // 20480
#define PSMEM_H (HSTAGE * HSTAGE_BYTES)        // 81920

template <int MODE>
__device__ __forceinline__ void pgemm_h(
    const __half* __restrict__ A, const __half* __restrict__ B, float* __restrict__ C,
    int m0, int n0, int K, int lda, int ldb, int ldc)
{
    extern __shared__ float dsm[];
    const uint32_t sbase = smem_u32(dsm);

    const int tid = threadIdx.x;
    const int arow = tid >> 2;          // 0..31 (rows arow + 32*i)
    const int ac = (tid & 3) << 3;      // half offset within row: 0,8,16,24

    const int warp = tid >> 5;
    const int lane = tid & 31;
    const int wm = (warp & 1) << 6;     // 0,64
    const int wn = (warp >> 1) << 6;    // 0,64
    const int g  = lane >> 2;
    const int tg = lane & 3;

    float acc[4][8][4];
#pragma unroll
    for (int i = 0; i < 4; i++)
#pragma unroll
        for (int j = 0; j < 8; j++)
#pragma unroll
            for (int l = 0; l < 4; l++) acc[i][j][l] = 0.f;

    const int nk = K / HBK;

#define HLOAD(s) do {                                                              \
        const uint32_t sa_u = sbase + (uint32_t)((s) & (HSTAGE - 1)) * HSTAGE_BYTES; \
        const uint32_t sb_u = sa_u + HT_BYTES;                                     \
        const __half* pa_ = A + (size_t)(m0 + arow) * lda + (s) * HBK + ac;        \
        const __half* pb_ = B + (size_t)(n0 + arow) * ldb + (s) * HBK + ac;        \
        _Pragma("unroll")                                                          \
        for (int r_ = 0; r_ < 128; r_ += 32) {                                     \
            CP_ASYNC16(sa_u + (uint32_t)((arow + r_) * HSTR + ac) * 2u,            \
                       pa_ + (size_t)r_ * lda);                                    \
            CP_ASYNC16(sb_u + (uint32_t)((arow + r_) * HSTR + ac) * 2u,            \
                       pb_ + (size_t)r_ * ldb);                                    \
        }                                                                          \
    } while (0)

#pragma unroll
    for (int s = 0; s < HSTAGE - 1; s++) {
        if (s < nk) HLOAD(s);
        CP_COMMIT();
    }

    for (int kt = 0; kt < nk; kt++) {
        CP_WAIT(HSTAGE - 2);
        __syncthreads();
        if (kt + HSTAGE - 1 < nk) HLOAD(kt + HSTAGE - 1);
        CP_COMMIT();

        const uint32_t* sa = (const uint32_t*)dsm + (size_t)(kt & (HSTAGE - 1)) * (HSTAGE_BYTES / 4);
        const uint32_t* sb = sa + HT_BYTES / 4;

#pragma unroll
        for (int ks = 0; ks < 2; ks++) {
            const int kb = ks * 8;
            uint32_t af[4][4];
#pragma unroll
            for (int mt = 0; mt < 4; mt++) {
                const uint32_t* base = &sa[(wm + mt * 16 + g) * HSTRW + kb + tg];
                af[mt][0] = base[0];
                af[mt][1] = base[8 * HSTRW];
                af[mt][2] = base[4];
                af[mt][3] = base[8 * HSTRW + 4];
            }
            uint32_t bf[8][2];
#pragma unroll
            for (int nt = 0; nt < 8; nt++) {
                const uint32_t* base = &sb[(wn + nt * 8 + g) * HSTRW + kb + tg];
                bf[nt][0] = base[0];
                bf[nt][1] = base[4];
            }
#pragma unroll
            for (int mt = 0; mt < 4; mt++)
#pragma unroll
                for (int nt = 0; nt < 8; nt++)
                    mma16(acc[mt][nt], af[mt], bf[nt]);
        }
        __syncthreads();
    }

#pragma unroll
    for (int mt = 0; mt < 4; mt++) {
        const int r = m0 + wm + mt * 16 + g;
#pragma unroll
        for (int nt = 0; nt < 8; nt++) {
            const int c = n0 + wn + nt * 8 + (tg << 1);
            const float v0 = acc[mt][nt][0], v1 = acc[mt][nt][1];
            const float v2 = acc[mt][nt][2], v3 = acc[mt][nt][3];
            if (MODE == 0) {
                float* p0 = C + (size_t)r * ldc + c;
                *(float2*)p0 = make_float2(v0, v1);
                float* p1 = p0 + (size_t)8 * ldc;
                *(float2*)p1 = make_float2(v2, v3);
            } else {
                // V transposed: g_v16t[(b*KLD + c)*SEQ + s]
                const int b = r >> 11, s = r & (SEQ - 1);
                const size_t base = ((size_t)b * KLD + c) * SEQ + s;
                g_v16t[base]           = __float2half_rn(v0);
                g_v16t[base + SEQ]     = __float2half_rn(v1);
                g_v16t[base + 8]       = __float2half_rn(v2);
                g_v16t[base + SEQ + 8] = __float2half_rn(v3);
            }
        }
    }
#undef HLOAD
}

// ---------------- projection wrappers ----------------------------------------
// merged QKV: grid (48, 32); x: [0,32)->Q, [32,40)->K, [40,48)->V (transposed)
__global__ void __launch_bounds__(128, 2) k_proj_qkv() {
    const int nb = blockIdx.x;
    const int m0 = blockIdx.y * 128;
    if (nb < 32) {
        pgemm_h<0>(g_hs16, g_wq16, g_q, m0, nb * 128, HDIM, HDIM, HDIM, QLD);
    } else if (nb < 40) {
        pgemm_h<0>(g_hs16, g_wk16, g_k, m0, (nb - 32) * 128, HDIM, HDIM, HDIM, KLD);
    } else {
        pgemm_h<1>(g_hs16, g_wv16, nullptr, m0, (nb - 40) * 128, HDIM, HDIM, HDIM, 0);
    }
}
__global__ void __launch_bounds__(128, 2) k_out_proj(float* __restrict__ out) {
    pgemm_h<0>(g_attn16, g_wo16, out, blockIdx.y * 128, blockIdx.x * 128, QLD, QLD, HDIM, HDIM);
}

// ============================================================================
// Fused flash attention (causal, online softmax), fp16 mma throughout.
// Grid (16 q-blocks [reversed], 64 z).  256 threads = 8 warps, 16 Q rows each.
// Q pre-scaled by 1/sqrt(HD) in rope_q.  V read transposed from g_v16t.
// smem: Q staged once (stride 136 halves), then double-buffered K (64x128,
// stride 136) + V^T (128x64, stride 72).
// ============================================================================
#define KSTRW 68                    // K/Q smem row stride in words (136 halves)
#define VSTRW 36                    // V^T smem row stride in words (72 halves)
#define K_TILE_W (64 * KSTRW)       // 4352 words
#define V_TILE_W (128 * VSTRW)      // 4608 words
#define FSMEM ((2 * K_TILE_W + 2 * V_TILE_W) * 4)   // 71680 bytes

__global__ void __launch_bounds__(256, 1) k_flash() {
    extern __shared__ uint32_t fsm[];
    const uint32_t sbase = smem_u32(fsm);

    const int tid = threadIdx.x;
    const int wid = tid >> 5, lane = tid & 31;
    const int g = lane >> 2, tg = lane & 3;
    const int wm = wid * 16;

    const int z = blockIdx.y, b = z >> 5, h = z & 31, kvh = h >> 2;
    const int qb = (int)(gridDim.x - 1 - blockIdx.x);
    const int q0 = qb * 128;
    const int nkv = 2 * qb + 2;

    const __half* Qp = g_q16 + (size_t)(b * SEQ + q0) * QLD + h * HD;
    const __half* Kp = g_k16 + (size_t)b * SEQ * KLD + kvh * HD;
    const __half* Vt = g_v16t + (size_t)(b * NKV + kvh) * HD * SEQ;

    // ---- stage Q tile (128 rows x 128 halves, stride 136 halves)
#pragma unroll
    for (int i = 0; i < 8; i++) {
        const int op = tid + i * 256;          // 0..2047
        const int row = op >> 4, ch = op & 15; // 16 x 16B chunks per row
        CP_ASYNC16(sbase + (uint32_t)(row * 272 + ch * 16), Qp + (size_t)row * QLD + ch * 8);
    }
    CP_COMMIT();
    CP_WAIT(0);
    __syncthreads();

    uint32_t qf[8][4];   // fp16 A fragments, 8 k16 steps over d=128
#pragma unroll
    for (int ks = 0; ks < 8; ks++) {
        const uint32_t* bp = fsm + (wm + g) * KSTRW + ks * 8 + tg;
        qf[ks][0] = bp[0];
        qf[ks][1] = bp[8 * KSTRW];
        qf[ks][2] = bp[4];
        qf[ks][3] = bp[8 * KSTRW + 4];
    }
    __syncthreads();

    const uint32_t* kbw[2] = { fsm, fsm + K_TILE_W };
    const uint32_t* vbw[2] = { fsm + 2 * K_TILE_W, fsm + 2 * K_TILE_W + V_TILE_W };
    const uint32_t kbu[2] = { sbase, sbase + K_TILE_W * 4u };
    const uint32_t vbu[2] = { sbase + 2u * K_TILE_W * 4u,
                              sbase + 2u * K_TILE_W * 4u + V_TILE_W * 4u };

#define LOAD_KV(t) do {                                                          \
        const int kv0_ = (t) * 64, p_ = (t) & 1;                                 \
        _Pragma("unroll")                                                        \
        for (int i_ = 0; i_ < 4; i_++) {                                         \
            const int op_ = tid + i_ * 256;          /* 0..1023 */               \
            const int krow_ = op_ >> 4, kch_ = op_ & 15;                         \
            CP_ASYNC16(kbu[p_] + (uint32_t)(krow_ * 272 + kch_ * 16),            \
                       Kp + (size_t)(kv0_ + krow_) * KLD + kch_ * 8);            \
            const int vrow_ = op_ >> 3, vch_ = op_ & 7;                          \
            CP_ASYNC16(vbu[p_] + (uint32_t)(vrow_ * 144 + vch_ * 16),            \
                       Vt + (size_t)vrow_ * SEQ + kv0_ + vch_ * 8);              \
        }                                                                        \
        CP_COMMIT();                                                             \
    } while (0)

    LOAD_KV(0);
    LOAD_KV(1);

    float mrow0 = -1e30f, mrow1 = -1e30f;
    float lrow0 = 0.f, lrow1 = 0.f;
    float o[16][4];
#pragma unroll
    for (int i = 0; i < 16; i++)
#pragma unroll
        for (int j = 0; j < 4; j++) o[i][j] = 0.f;

    const int r0g = q0 + wm + g, r1g = r0g + 8;

    for (int t = 0; t < nkv; t++) {
        const int p = t & 1, kv0 = t * 64;
        if (t + 1 < nkv) { CP_WAIT(1); } else { CP_WAIT(0); }
        __syncthreads();

        // ---- S = Q K^T  (16 Q rows x 64 KV cols per warp, fp16 mma)
        float sacc[8][4];
#pragma unroll
        for (int nt = 0; nt < 8; nt++)
#pragma unroll
            for (int j = 0; j < 4; j++) sacc[nt][j] = 0.f;

        const uint32_t* kb = kbw[p];
#pragma unroll
        for (int ks = 0; ks < 8; ks++) {
#pragma unroll
            for (int nt = 0; nt < 8; nt++) {
                uint32_t bf[2];
                const uint32_t* bp = kb + (nt * 8 + g) * KSTRW + ks * 8 + tg;
                bf[0] = bp[0];
                bf[1] = bp[4];
                mma16(sacc[nt], qf[ks], bf);
            }
        }

        // ---- causal mask + row max
        float mnew0 = mrow0, mnew1 = mrow1;
        const bool domask = (kv0 + 63 > q0);
#pragma unroll
        for (int nt = 0; nt < 8; nt++) {
            const int c0 = kv0 + nt * 8 + 2 * tg, c1 = c0 + 1;
            float v0 = sacc[nt][0], v1 = sacc[nt][1];
            float v2 = sacc[nt][2], v3 = sacc[nt][3];
            if (domask) {
                if (c0 > r0g) v0 = -1e30f;
                if (c1 > r0g) v1 = -1e30f;
                if (c0 > r1g) v2 = -1e30f;
                if (c1 > r1g) v3 = -1e30f;
            }
            sacc[nt][0] = v0; sacc[nt][1] = v1; sacc[nt][2] = v2; sacc[nt][3] = v3;
            mnew0 = fmaxf(mnew0, fmaxf(v0, v1));
            mnew1 = fmaxf(mnew1, fmaxf(v2, v3));
        }
        mnew0 = fmaxf(mnew0, __shfl_xor_sync(0xffffffffu, mnew0, 1));
        mnew0 = fmaxf(mnew0, __shfl_xor_sync(0xffffffffu, mnew0, 2));
        mnew1 = fmaxf(mnew1, __shfl_xor_sync(0xffffffffu, mnew1, 1));
        mnew1 = fmaxf(mnew1, __shfl_xor_sync(0xffffffffu, mnew1, 2));

        const float f0 = __expf(mrow0 - mnew0);
        const float f1 = __expf(mrow1 - mnew1);

        float rs0 = 0.f, rs1 = 0.f;
#pragma unroll
        for (int nt = 0; nt < 8; nt++) {
            const float e0 = __expf(sacc[nt][0] - mnew0);
            const float e1 = __expf(sacc[nt][1] - mnew0);
            const float e2 = __expf(sacc[nt][2] - mnew1);
            const float e3 = __expf(sacc[nt][3] - mnew1);
            sacc[nt][0] = e0; sacc[nt][1] = e1; sacc[nt][2] = e2; sacc[nt][3] = e3;
            rs0 += e0 + e1;
            rs1 += e2 + e3;
        }
        rs0 += __shfl_xor_sync(0xffffffffu, rs0, 1);
        rs0 += __shfl_xor_sync(0xffffffffu, rs0, 2);
        rs1 += __shfl_xor_sync(0xffffffffu, rs1, 1);
        rs1 += __shfl_xor_sync(0xffffffffu, rs1, 2);

        lrow0 = lrow0 * f0 + rs0;
        lrow1 = lrow1 * f1 + rs1;
        mrow0 = mnew0;
        mrow1 = mnew1;

#pragma unroll
        for (int nt2 = 0; nt2 < 16; nt2++) {
            o[nt2][0] *= f0; o[nt2][1] *= f0;
            o[nt2][2] *= f1; o[nt2][3] *= f1;
        }

        // ---- O += P V  (P fragments = packed C accumulators; NO shuffles)
        const uint32_t* vb = vbw[p];
#pragma unroll
        for (int ks2 = 0; ks2 < 4; ks2++) {
            uint32_t pa[4];
            pa[0] = packh2(sacc[2 * ks2][0],     sacc[2 * ks2][1]);
            pa[1] = packh2(sacc[2 * ks2][2],     sacc[2 * ks2][3]);
            pa[2] = packh2(sacc[2 * ks2 + 1][0], sacc[2 * ks2 + 1][1]);
            pa[3] = packh2(sacc[2 * ks2 + 1][2], sacc[2 * ks2 + 1][3]);
#pragma unroll
            for (int nt2 = 0; nt2 < 16; nt2++) {
                uint32_t bf[2];
                const uint32_t* bp = vb + (nt2 * 8 + g) * VSTRW + ks2 * 8 + tg;
                bf[0] = bp[0];
                bf[1] = bp[4];
                mma16(o[nt2], pa, bf);
            }
        }

        __syncthreads();
        if (t + 2 < nkv) LOAD_KV(t + 2);
    }

    // epilogue: normalize, fp16 out (feeds out_proj A operand)
    const float inv0 = 1.f / lrow0;
    const float inv1 = 1.f / lrow1;
    __half* orow0 = g_attn16 + (size_t)(b * SEQ + r0g) * QLD + h * HD;
    __half* orow1 = g_attn16 + (size_t)(b * SEQ + r1g) * QLD + h * HD;
#pragma unroll
    for (int nt2 = 0; nt2 < 16; nt2++) {
        const int c = nt2 * 8 + 2 * tg;
        *(__half2*)(orow0 + c) = __floats2half2_rn(o[nt2][0] * inv0, o[nt2][1] * inv0);
        *(__half2*)(orow1 + c) = __floats2half2_rn(o[nt2][2] * inv1, o[nt2][3] * inv1);
    }
#undef LOAD_KV
}

// ---------------- fp32 -> fp16 prepass (MLP=4) --------------------------------
__global__ void cvt_half4(uint4* __restrict__ dst, const float4* __restrict__ src) {
    const size_t base = (size_t)blockIdx.x * 1024 + threadIdx.x;
#pragma unroll
    for (int i = 0; i < 4; i++) {
        const size_t oi = base + i * 256;
        const float4 a = src[2 * oi];
        const float4 b = src[2 * oi + 1];
        __half2 h0 = __floats2half2_rn(a.x, a.y);
        __half2 h1 = __floats2half2_rn(a.z, a.w);
        __half2 h2 = __floats2half2_rn(b.x, b.y);
        __half2 h3 = __floats2half2_rn(b.z, b.w);
        uint4 o4;
        o4.x = *(uint32_t*)&h0;
        o4.y = *(uint32_t*)&h1;
        o4.z = *(uint32_t*)&h2;
        o4.w = *(uint32_t*)&h3;
        dst[oi] = o4;
    }
}

// ---------------- RoPE: fp32 in -> fp16 out (q also scaled by 1/sqrt(HD)) -----
__global__ void rope_q(const float* __restrict__ cosT, const float* __restrict__ sinT) {
    const int row = blockIdx.x;
    const int s = row & (SEQ - 1);
    const float sc = 0.08838834764831845f;   // 1/sqrt(128)
    const float* cr = cosT + (size_t)s * HD;
    const float* sr = sinT + (size_t)s * HD;
    const float* base = g_q + (size_t)row * QLD;
    __half* ob = g_q16 + (size_t)row * QLD;
    for (int idx = threadIdx.x; idx < NH * 64; idx += blockDim.x) {
        const int hh = idx >> 6, d = idx & 63;
        const float* p = base + hh * HD;
        __half* q = ob + hh * HD;
        const float x1 = p[d], x2 = p[d + 64];
        q[d]      = __float2half_rn((x1 * cr[d]      - x2 * sr[d])      * sc);
        q[d + 64] = __float2half_rn((x2 * cr[d + 64] + x1 * sr[d + 64]) * sc);
    }
}
__global__ void rope_k(const float* __restrict__ cosT, const float* __restrict__ sinT) {
    const int row = blockIdx.x;
    const int s = row & (SEQ - 1);
    const float* cr = cosT + (size_t)s * HD;
    const float* sr = sinT + (size_t)s * HD;
    const float* base = g_k + (size_t)row * KLD;
    __half* ob = g_k16 + (size_t)row * KLD;
    for (int idx = threadIdx.x; idx < NKV * 64; idx += blockDim.x) {
        const int hh = idx >> 6, d = idx & 63;
        const float* p = base + hh * HD;
        __half* q = ob + hh * HD;
        const float x1 = p[d], x2 = p[d + 64];
        q[d]      = __float2half_rn(x1 * cr[d]      - x2 * sr[d]);
        q[d + 64] = __float2half_rn(x2 * cr[d + 64] + x1 * sr[d + 64]);
    }
}

// ---------------- launch -----------------------------------------------------
extern "C" void kernel_launch(void* const* d_in, const int* in_sizes, int n_in,
                              void* d_out, int out_size) {
    (void)in_sizes; (void)n_in; (void)out_size;
    const float* hs   = (const float*)d_in[0];
    const float* Wq   = (const float*)d_in[1];
    const float* Wk   = (const float*)d_in[2];
    const float* Wv   = (const float*)d_in[3];
    const float* Wo   = (const float*)d_in[4];
    const float* cosT = (const float*)d_in[5];
    const float* sinT = (const float*)d_in[6];
    float* out = (float*)d_out;

    static bool attr_set = false;
    if (!attr_set) {
        cudaFuncSetAttribute(k_proj_qkv, cudaFuncAttributeMaxDynamicSharedMemorySize, PSMEM_H);
        cudaFuncSetAttribute(k_out_proj, cudaFuncAttributeMaxDynamicSharedMemorySize, PSMEM_H);
        cudaFuncSetAttribute(k_flash,    cudaFuncAttributeMaxDynamicSharedMemorySize, FSMEM);
        attr_set = true;
    }

    void* phs;  cudaGetSymbolAddress(&phs, g_hs16);
    void* pwq;  cudaGetSymbolAddress(&pwq, g_wq16);
    void* pwk;  cudaGetSymbolAddress(&pwk, g_wk16);
    void* pwv;  cudaGetSymbolAddress(&pwv, g_wv16);
    void* pwo;  cudaGetSymbolAddress(&pwo, g_wo16);

    cvt_half4<<<((size_t)ROWS * HDIM) / 8192, 256>>>((uint4*)phs, (const float4*)hs);
    cvt_half4<<<((size_t)QLD * HDIM) / 8192, 256>>>((uint4*)pwq, (const float4*)Wq);
    cvt_half4<<<((size_t)KLD * HDIM) / 8192, 256>>>((uint4*)pwk, (const float4*)Wk);
    cvt_half4<<<((size_t)KLD * HDIM) / 8192, 256>>>((uint4*)pwv, (const float4*)Wv);
    cvt_half4<<<((size_t)HDIM * QLD) / 8192, 256>>>((uint4*)pwo, (const float4*)Wo);

    k_proj_qkv<<<dim3(48, ROWS / 128), 128, PSMEM_H>>>();
    rope_q<<<ROWS, 256>>>(cosT, sinT);
    rope_k<<<ROWS, 256>>>(cosT, sinT);
    k_flash<<<dim3(SEQ / 128, NBH), 256, FSMEM>>>();
    k_out_proj<<<dim3(HDIM / 128, ROWS / 128), 128, PSMEM_H>>>(out);
}

// round 10
// speedup vs baseline: 2.3647x; 1.1390x over previous
#include <cuda_runtime.h>
#include <cuda_fp16.h>
#include <cstdint>

#define SEQ 2048
#define NB 2
#define ROWS (NB * SEQ)      // 4096 total (b,s) rows
#define HDIM 4096
#define NH 32
#define NKV 8
#define HD 128
#define QLD (NH * HD)        // 4096
#define KLD (NKV * HD)       // 1024
#define NBH (NB * NH)        // 64

// ---------------- scratch (static device allocations; no cudaMalloc) -------
__device__ float g_q[(size_t)ROWS * QLD];                 // fp32 proj out
__device__ float g_k[(size_t)ROWS * KLD];
__device__ __half g_hs16[(size_t)ROWS * HDIM];
__device__ __half g_wq16[(size_t)QLD * HDIM];
__device__ __half g_wk16[(size_t)KLD * HDIM];
__device__ __half g_wv16[(size_t)KLD * HDIM];
__device__ __half g_wo16[(size_t)HDIM * QLD];
__device__ __half g_q16[(size_t)ROWS * QLD];              // rope out, scaled
__device__ __half g_k16[(size_t)ROWS * KLD];              // rope out
__device__ __half g_v16t[(size_t)NB * KLD * SEQ];         // V transposed [b][kv][d][s]
__device__ __half g_attn16[(size_t)ROWS * QLD];           // flash out

// ---------------- helpers ---------------------------------------------------
__device__ __forceinline__ uint32_t smem_u32(const void* p) {
    uint32_t a;
    asm("{ .reg .u64 t; cvta.to.shared.u64 t, %1; cvt.u32.u64 %0, t; }" : "=r"(a) : "l"(p));
    return a;
}
__device__ __forceinline__ uint32_t packh2(float a, float b) {
    __half2 h = __floats2half2_rn(a, b);
    return *(uint32_t*)&h;
}

#define CP_ASYNC16(dst, src) \
    asm volatile("cp.async.cg.shared.global [%0], [%1], 16;" :: "r"(dst), "l"(src) : "memory")
#define CP_COMMIT() asm volatile("cp.async.commit_group;" ::: "memory")
#define CP_WAIT(n)  asm volatile("cp.async.wait_group %0;" :: "n"(n) : "memory")

// ldmatrix x4: loads 4 8x8 b16 matrices; lane l supplies row (l&7) addr of matrix (l>>3)
#define LDSM4(r0, r1, r2, r3, addr) \
    asm volatile("ldmatrix.sync.aligned.m8n8.x4.shared.b16 {%0,%1,%2,%3}, [%4];" \
        : "=r"(r0), "=r"(r1), "=r"(r2), "=r"(r3) : "r"(addr))

// fp16 mma: 16x8x16, fp32 accumulate
__device__ __forceinline__ void mma16(float* c, const uint32_t* a, const uint32_t* b) {
    asm volatile(
        "mma.sync.aligned.m16n8k16.row.col.f32.f16.f16.f32 "
        "{%0,%1,%2,%3}, {%4,%5,%6,%7}, {%8,%9}, {%0,%1,%2,%3};\n"
        : "+f"(c[0]), "+f"(c[1]), "+f"(c[2]), "+f"(c[3])
        : "r"(a[0]), "r"(a[1]), "r"(a[2]), "r"(a[3]), "r"(b[0]), "r"(b[1]));
}

// ============================================================================
// Projection GEMM (fp16 operands): C[128,128] tile = A * B^T.
// A [M,K], B [N,K] row-major __half.  128 threads = 4 warps (2m x 2n),
// warp tile 64x64.  BK=32, 4-stage cp.async, 2 CTAs/SM.
// Fragments via ldmatrix.x4 (stride 40 halves = 80B rows, conflict-free).
// MODE 0: fp32 C out.  MODE 1: V-transposed fp16 out -> g_v16t.
// ============================================================================
#define HBK 32
#define HSTAGE 4
#define HSTR 40                                // halves
#define HT_BYTES (128 * HSTR * 2)              // 10240 per tile
#define HSTAGE_BYTES (2 * HT_BYTES)            // 20480
#define PSMEM_H (HSTAGE * HSTAGE_BYTES)        // 81920

template <int MODE>
__device__ __forceinline__ void pgemm_h(
    const __half* __restrict__ A, const __half* __restrict__ B, float* __restrict__ C,
    int m0, int n0, int K, int lda, int ldb, int ldc)
{
    extern __shared__ float dsm[];
    const uint32_t sbase = smem_u32(dsm);

    const int tid = threadIdx.x;
    const int arow = tid >> 2;          // 0..31
    const int ac = (tid & 3) << 3;      // 0,8,16,24 halves

    const int warp = tid >> 5;
    const int lane = tid & 31;
    const int wm = (warp & 1) << 6;     // 0,64
    const int wn = (warp >> 1) << 6;    // 0,64
    const int g  = lane >> 2;
    const int tg = lane & 3;

    // ldmatrix per-lane address components
    const int lrA = (((lane >> 3) & 1) << 3) + (lane & 7);   // row sel: bit3
    const int lkA = (lane >> 4) << 3;                        // k half sel: bit4
    const int lrB = (((lane >> 4) & 1) << 3) + (lane & 7);   // row sel: bit4
    const int lkB = ((lane >> 3) & 1) << 3;                  // k half sel: bit3

    uint32_t offA[4], offB[4];
#pragma unroll
    for (int mt = 0; mt < 4; mt++)
        offA[mt] = (uint32_t)(((wm + mt * 16 + lrA) * HSTR + lkA) * 2);
#pragma unroll
    for (int np = 0; np < 4; np++)
        offB[np] = (uint32_t)(((wn + np * 16 + lrB) * HSTR + lkB) * 2) + HT_BYTES;

    float acc[4][8][4];
#pragma unroll
    for (int i = 0; i < 4; i++)
#pragma unroll
        for (int j = 0; j < 8; j++)
#pragma unroll
            for (int l = 0; l < 4; l++) acc[i][j][l] = 0.f;

    const int nk = K / HBK;

#define HLOAD(s) do {                                                              \
        const uint32_t sa_u = sbase + (uint32_t)((s) & (HSTAGE - 1)) * HSTAGE_BYTES; \
        const uint32_t sb_u = sa_u + HT_BYTES;                                     \
        const __half* pa_ = A + (size_t)(m0 + arow) * lda + (s) * HBK + ac;        \
        const __half* pb_ = B + (size_t)(n0 + arow) * ldb + (s) * HBK + ac;        \
        _Pragma("unroll")                                                          \
        for (int r_ = 0; r_ < 128; r_ += 32) {                                     \
            CP_ASYNC16(sa_u + (uint32_t)((arow + r_) * HSTR + ac) * 2u,            \
                       pa_ + (size_t)r_ * lda);                                    \
            CP_ASYNC16(sb_u + (uint32_t)((arow + r_) * HSTR + ac) * 2u,            \
                       pb_ + (size_t)r_ * ldb);                                    \
        }                                                                          \
    } while (0)

#pragma unroll
    for (int s = 0; s < HSTAGE - 1; s++) {
        if (s < nk) HLOAD(s);
        CP_COMMIT();
    }

    for (int kt = 0; kt < nk; kt++) {
        CP_WAIT(HSTAGE - 2);
        __syncthreads();
        if (kt + HSTAGE - 1 < nk) HLOAD(kt + HSTAGE - 1);
        CP_COMMIT();

        const uint32_t st_u = sbase + (uint32_t)((kt & (HSTAGE - 1)) * HSTAGE_BYTES);

#pragma unroll
        for (int ks = 0; ks < 2; ks++) {
            const uint32_t kadd = ks * 32;     // +16 halves per k16 step
            uint32_t af[4][4];
#pragma unroll
            for (int mt = 0; mt < 4; mt++)
                LDSM4(af[mt][0], af[mt][1], af[mt][2], af[mt][3],
                      st_u + offA[mt] + kadd);
            uint32_t bf[8][2];
#pragma unroll
            for (int np = 0; np < 4; np++)
                LDSM4(bf[2 * np][0], bf[2 * np][1], bf[2 * np + 1][0], bf[2 * np + 1][1],
                      st_u + offB[np] + kadd);
#pragma unroll
            for (int mt = 0; mt < 4; mt++)
#pragma unroll
                for (int nt = 0; nt < 8; nt++)
                    mma16(acc[mt][nt], af[mt], bf[nt]);
        }
        __syncthreads();
    }

#pragma unroll
    for (int mt = 0; mt < 4; mt++) {
        const int r = m0 + wm + mt * 16 + g;
#pragma unroll
        for (int nt = 0; nt < 8; nt++) {
            const int c = n0 + wn + nt * 8 + (tg << 1);
            const float v0 = acc[mt][nt][0], v1 = acc[mt][nt][1];
            const float v2 = acc[mt][nt][2], v3 = acc[mt][nt][3];
            if (MODE == 0) {
                float* p0 = C + (size_t)r * ldc + c;
                *(float2*)p0 = make_float2(v0, v1);
                float* p1 = p0 + (size_t)8 * ldc;
                *(float2*)p1 = make_float2(v2, v3);
            } else {
                const int b = r >> 11, s = r & (SEQ - 1);
                const size_t base = ((size_t)b * KLD + c) * SEQ + s;
                g_v16t[base]           = __float2half_rn(v0);
                g_v16t[base + SEQ]     = __float2half_rn(v1);
                g_v16t[base + 8]       = __float2half_rn(v2);
                g_v16t[base + SEQ + 8] = __float2half_rn(v3);
            }
        }
    }
#undef HLOAD
}

// ---------------- projection wrappers ----------------------------------------
__global__ void __launch_bounds__(128, 2) k_proj_qkv() {
    const int nb = blockIdx.x;
    const int m0 = blockIdx.y * 128;
    if (nb < 32) {
        pgemm_h<0>(g_hs16, g_wq16, g_q, m0, nb * 128, HDIM, HDIM, HDIM, QLD);
    } else if (nb < 40) {
        pgemm_h<0>(g_hs16, g_wk16, g_k, m0, (nb - 32) * 128, HDIM, HDIM, HDIM, KLD);
    } else {
        pgemm_h<1>(g_hs16, g_wv16, nullptr, m0, (nb - 40) * 128, HDIM, HDIM, HDIM, 0);
    }
}
__global__ void __launch_bounds__(128, 2) k_out_proj(float* __restrict__ out) {
    pgemm_h<0>(g_attn16, g_wo16, out, blockIdx.y * 128, blockIdx.x * 128, QLD, QLD, HDIM, HDIM);
}

// ============================================================================
// Fused flash attention (causal, online softmax), fp16 mma, ldmatrix frags.
// Grid (16 q-blocks [reversed], 64 z).  256 threads = 8 warps, 16 Q rows each.
// Q pre-scaled by 1/sqrt(HD) in rope_q.  V read transposed from g_v16t.
// ============================================================================
#define KSTRW 68                    // K/Q smem row stride words (136 halves, 272B)
#define VSTRW 36                    // V^T row stride words (72 halves, 144B)
#define K_TILE_W (64 * KSTRW)       // 4352 words
#define V_TILE_W (128 * VSTRW)      // 4608 words
#define FSMEM ((2 * K_TILE_W + 2 * V_TILE_W) * 4)   // 71680 bytes

__global__ void __launch_bounds__(256, 1) k_flash() {
    extern __shared__ uint32_t fsm[];
    const uint32_t sbase = smem_u32(fsm);

    const int tid = threadIdx.x;
    const int wid = tid >> 5, lane = tid & 31;
    const int g = lane >> 2, tg = lane & 3;
    const int wm = wid * 16;

    const int z = blockIdx.y, b = z >> 5, h = z & 31, kvh = h >> 2;
    const int qb = (int)(gridDim.x - 1 - blockIdx.x);
    const int q0 = qb * 128;
    const int nkv = 2 * qb + 2;

    const __half* Qp = g_q16 + (size_t)(b * SEQ + q0) * QLD + h * HD;
    const __half* Kp = g_k16 + (size_t)b * SEQ * KLD + kvh * HD;
    const __half* Vt = g_v16t + (size_t)(b * NKV + kvh) * HD * SEQ;

    // ldmatrix per-lane address components (B-operand pattern)
    const int lrB = (((lane >> 4) & 1) << 3) + (lane & 7);
    const int lkB = ((lane >> 3) & 1) << 3;                  // halves
    // A-operand pattern (for Q fragments)
    const int lrA = (((lane >> 3) & 1) << 3) + (lane & 7);
    const int lkA = (lane >> 4) << 3;

    // ---- stage Q tile (128 rows x 128 halves, 272B row stride)
#pragma unroll
    for (int i = 0; i < 8; i++) {
        const int op = tid + i * 256;
        const int row = op >> 4, ch = op & 15;
        CP_ASYNC16(sbase + (uint32_t)(row * 272 + ch * 16), Qp + (size_t)row * QLD + ch * 8);
    }
    CP_COMMIT();
    CP_WAIT(0);
    __syncthreads();

    uint32_t qf[8][4];   // A fragments, 8 k16 steps over d=128
    {
        const uint32_t qoff = sbase + (uint32_t)((wm + lrA) * 272 + lkA * 2);
#pragma unroll
        for (int ks = 0; ks < 8; ks++)
            LDSM4(qf[ks][0], qf[ks][1], qf[ks][2], qf[ks][3], qoff + ks * 32);
    }
    __syncthreads();

    const uint32_t kbu[2] = { sbase, sbase + K_TILE_W * 4u };
    const uint32_t vbu[2] = { sbase + 2u * K_TILE_W * 4u,
                              sbase + 2u * K_TILE_W * 4u + V_TILE_W * 4u };

    uint32_t offK[4], offV[8];
#pragma unroll
    for (int np = 0; np < 4; np++)
        offK[np] = (uint32_t)((np * 16 + lrB) * 272 + lkB * 2);
#pragma unroll
    for (int np = 0; np < 8; np++)
        offV[np] = (uint32_t)((np * 16 + lrB) * 144 + lkB * 2);

#define LOAD_KV(t) do {                                                          \
        const int kv0_ = (t) * 64, p_ = (t) & 1;                                 \
        _Pragma("unroll")                                                        \
        for (int i_ = 0; i_ < 4; i_++) {                                         \
            const int op_ = tid + i_ * 256;                                      \
            const int krow_ = op_ >> 4, kch_ = op_ & 15;                         \
            CP_ASYNC16(kbu[p_] + (uint32_t)(krow_ * 272 + kch_ * 16),            \
                       Kp + (size_t)(kv0_ + krow_) * KLD + kch_ * 8);            \
            const int vrow_ = op_ >> 3, vch_ = op_ & 7;                          \
            CP_ASYNC16(vbu[p_] + (uint32_t)(vrow_ * 144 + vch_ * 16),            \
                       Vt + (size_t)vrow_ * SEQ + kv0_ + vch_ * 8);              \
        }                                                                        \
        CP_COMMIT();                                                             \
    } while (0)

    LOAD_KV(0);
    LOAD_KV(1);

    float mrow0 = -1e30f, mrow1 = -1e30f;
    float lrow0 = 0.f, lrow1 = 0.f;
    float o[16][4];
#pragma unroll
    for (int i = 0; i < 16; i++)
#pragma unroll
        for (int j = 0; j < 4; j++) o[i][j] = 0.f;

    const int r0g = q0 + wm + g, r1g = r0g + 8;

    for (int t = 0; t < nkv; t++) {
        const int p = t & 1, kv0 = t * 64;
        if (t + 1 < nkv) { CP_WAIT(1); } else { CP_WAIT(0); }
        __syncthreads();

        // ---- S = Q K^T
        float sacc[8][4];
#pragma unroll
        for (int nt = 0; nt < 8; nt++)
#pragma unroll
            for (int j = 0; j < 4; j++) sacc[nt][j] = 0.f;

#pragma unroll
        for (int ks = 0; ks < 8; ks++) {
            uint32_t bf[8][2];
#pragma unroll
            for (int np = 0; np < 4; np++)
                LDSM4(bf[2 * np][0], bf[2 * np][1], bf[2 * np + 1][0], bf[2 * np + 1][1],
                      kbu[p] + offK[np] + ks * 32);
#pragma unroll
            for (int nt = 0; nt < 8; nt++)
                mma16(sacc[nt], qf[ks], bf[nt]);
        }

        // ---- causal mask + row max
        float mnew0 = mrow0, mnew1 = mrow1;
        const bool domask = (kv0 + 63 > q0);
#pragma unroll
        for (int nt = 0; nt < 8; nt++) {
            const int c0 = kv0 + nt * 8 + 2 * tg, c1 = c0 + 1;
            float v0 = sacc[nt][0], v1 = sacc[nt][1];
            float v2 = sacc[nt][2], v3 = sacc[nt][3];
            if (domask) {
                if (c0 > r0g) v0 = -1e30f;
                if (c1 > r0g) v1 = -1e30f;
                if (c0 > r1g) v2 = -1e30f;
                if (c1 > r1g) v3 = -1e30f;
            }
            sacc[nt][0] = v0; sacc[nt][1] = v1; sacc[nt][2] = v2; sacc[nt][3] = v3;
            mnew0 = fmaxf(mnew0, fmaxf(v0, v1));
            mnew1 = fmaxf(mnew1, fmaxf(v2, v3));
        }
        mnew0 = fmaxf(mnew0, __shfl_xor_sync(0xffffffffu, mnew0, 1));
        mnew0 = fmaxf(mnew0, __shfl_xor_sync(0xffffffffu, mnew0, 2));
        mnew1 = fmaxf(mnew1, __shfl_xor_sync(0xffffffffu, mnew1, 1));
        mnew1 = fmaxf(mnew1, __shfl_xor_sync(0xffffffffu, mnew1, 2));

        const float f0 = __expf(mrow0 - mnew0);
        const float f1 = __expf(mrow1 - mnew1);

        float rs0 = 0.f, rs1 = 0.f;
#pragma unroll
        for (int nt = 0; nt < 8; nt++) {
            const float e0 = __expf(sacc[nt][0] - mnew0);
            const float e1 = __expf(sacc[nt][1] - mnew0);
            const float e2 = __expf(sacc[nt][2] - mnew1);
            const float e3 = __expf(sacc[nt][3] - mnew1);
            sacc[nt][0] = e0; sacc[nt][1] = e1; sacc[nt][2] = e2; sacc[nt][3] = e3;
            rs0 += e0 + e1;
            rs1 += e2 + e3;
        }
        rs0 += __shfl_xor_sync(0xffffffffu, rs0, 1);
        rs0 += __shfl_xor_sync(0xffffffffu, rs0, 2);
        rs1 += __shfl_xor_sync(0xffffffffu, rs1, 1);
        rs1 += __shfl_xor_sync(0xffffffffu, rs1, 2);

        lrow0 = lrow0 * f0 + rs0;
        lrow1 = lrow1 * f1 + rs1;
        mrow0 = mnew0;
        mrow1 = mnew1;

#pragma unroll
        for (int nt2 = 0; nt2 < 16; nt2++) {
            o[nt2][0] *= f0; o[nt2][1] *= f0;
            o[nt2][2] *= f1; o[nt2][3] *= f1;
        }

        // ---- O += P V  (P = packed C accumulators; V frags via ldmatrix)
#pragma unroll
        for (int ks2 = 0; ks2 < 4; ks2++) {
            uint32_t pa[4];
            pa[0] = packh2(sacc[2 * ks2][0],     sacc[2 * ks2][1]);
            pa[1] = packh2(sacc[2 * ks2][2],     sacc[2 * ks2][3]);
            pa[2] = packh2(sacc[2 * ks2 + 1][0], sacc[2 * ks2 + 1][1]);
            pa[3] = packh2(sacc[2 * ks2 + 1][2], sacc[2 * ks2 + 1][3]);
            uint32_t vf[16][2];
#pragma unroll
            for (int np = 0; np < 8; np++)
                LDSM4(vf[2 * np][0], vf[2 * np][1], vf[2 * np + 1][0], vf[2 * np + 1][1],
                      vbu[p] + offV[np] + ks2 * 32);
#pragma unroll
            for (int nt2 = 0; nt2 < 16; nt2++)
                mma16(o[nt2], pa, vf[nt2]);
        }

        __syncthreads();
        if (t + 2 < nkv) LOAD_KV(t + 2);
    }

    // epilogue: normalize, fp16 out
    const float inv0 = 1.f / lrow0;
    const float inv1 = 1.f / lrow1;
    __half* orow0 = g_attn16 + (size_t)(b * SEQ + r0g) * QLD + h * HD;
    __half* orow1 = g_attn16 + (size_t)(b * SEQ + r1g) * QLD + h * HD;
#pragma unroll
    for (int nt2 = 0; nt2 < 16; nt2++) {
        const int c = nt2 * 8 + 2 * tg;
        *(__half2*)(orow0 + c) = __floats2half2_rn(o[nt2][0] * inv0, o[nt2][1] * inv0);
        *(__half2*)(orow1 + c) = __floats2half2_rn(o[nt2][2] * inv1, o[nt2][3] * inv1);
    }
#undef LOAD_KV
}

// ---------------- fp32 -> fp16 prepass (MLP=4) --------------------------------
__global__ void cvt_half4(uint4* __restrict__ dst, const float4* __restrict__ src) {
    const size_t base = (size_t)blockIdx.x * 1024 + threadIdx.x;
#pragma unroll
    for (int i = 0; i < 4; i++) {
        const size_t oi = base + i * 256;
        const float4 a = src[2 * oi];
        const float4 b = src[2 * oi + 1];
        __half2 h0 = __floats2half2_rn(a.x, a.y);
        __half2 h1 = __floats2half2_rn(a.z, a.w);
        __half2 h2 = __floats2half2_rn(b.x, b.y);
        __half2 h3 = __floats2half2_rn(b.z, b.w);
        uint4 o4;
        o4.x = *(uint32_t*)&h0;
        o4.y = *(uint32_t*)&h1;
        o4.z = *(uint32_t*)&h2;
        o4.w = *(uint32_t*)&h3;
        dst[oi] = o4;
    }
}

// ---------------- RoPE: fp32 in -> fp16 out (q also scaled by 1/sqrt(HD)) -----
__global__ void rope_q(const float* __restrict__ cosT, const float* __restrict__ sinT) {
    const int row = blockIdx.x;
    const int s = row & (SEQ - 1);
    const float sc = 0.08838834764831845f;
    const float* cr = cosT + (size_t)s * HD;
    const float* sr = sinT + (size_t)s * HD;
    const float* base = g_q + (size_t)row * QLD;
    __half* ob = g_q16 + (size_t)row * QLD;
    for (int idx = threadIdx.x; idx < NH * 64; idx += blockDim.x) {
        const int hh = idx >> 6, d = idx & 63;
        const float* p = base + hh * HD;
        __half* q = ob + hh * HD;
        const float x1 = p[d], x2 = p[d + 64];
        q[d]      = __float2half_rn((x1 * cr[d]      - x2 * sr[d])      * sc);
        q[d + 64] = __float2half_rn((x2 * cr[d + 64] + x1 * sr[d + 64]) * sc);
    }
}
__global__ void rope_k(const float* __restrict__ cosT, const float* __restrict__ sinT) {
    const int row = blockIdx.x;
    const int s = row & (SEQ - 1);
    const float* cr = cosT + (size_t)s * HD;
    const float* sr = sinT + (size_t)s * HD;
    const float* base = g_k + (size_t)row * KLD;
    __half* ob = g_k16 + (size_t)row * KLD;
    for (int idx = threadIdx.x; idx < NKV * 64; idx += blockDim.x) {
        const int hh = idx >> 6, d = idx & 63;
        const float* p = base + hh * HD;
        __half* q = ob + hh * HD;
        const float x1 = p[d], x2 = p[d + 64];
        q[d]      = __float2half_rn(x1 * cr[d]      - x2 * sr[d]);
        q[d + 64] = __float2half_rn(x2 * cr[d + 64] + x1 * sr[d + 64]);
    }
}

// ---------------- launch -----------------------------------------------------
extern "C" void kernel_launch(void* const* d_in, const int* in_sizes, int n_in,
                              void* d_out, int out_size) {
    (void)in_sizes; (void)n_in; (void)out_size;
    const float* hs   = (const float*)d_in[0];
    const float* Wq   = (const float*)d_in[1];
    const float* Wk   = (const float*)d_in[2];
    const float* Wv   = (const float*)d_in[3];
    const float* Wo   = (const float*)d_in[4];
    const float* cosT = (const float*)d_in[5];
    const float* sinT = (const float*)d_in[6];
    float* out = (float*)d_out;

    static bool attr_set = false;
    if (!attr_set) {
        cudaFuncSetAttribute(k_proj_qkv, cudaFuncAttributeMaxDynamicSharedMemorySize, PSMEM_H);
        cudaFuncSetAttribute(k_out_proj, cudaFuncAttributeMaxDynamicSharedMemorySize, PSMEM_H);
        cudaFuncSetAttribute(k_flash,    cudaFuncAttributeMaxDynamicSharedMemorySize, FSMEM);
        attr_set = true;
    }

    void* phs;  cudaGetSymbolAddress(&phs, g_hs16);
    void* pwq;  cudaGetSymbolAddress(&pwq, g_wq16);
    void* pwk;  cudaGetSymbolAddress(&pwk, g_wk16);
    void* pwv;  cudaGetSymbolAddress(&pwv, g_wv16);
    void* pwo;  cudaGetSymbolAddress(&pwo, g_wo16);

    cvt_half4<<<((size_t)ROWS * HDIM) / 8192, 256>>>((uint4*)phs, (const float4*)hs);
    cvt_half4<<<((size_t)QLD * HDIM) / 8192, 256>>>((uint4*)pwq, (const float4*)Wq);
    cvt_half4<<<((size_t)KLD * HDIM) / 8192, 256>>>((uint4*)pwk, (const float4*)Wk);
    cvt_half4<<<((size_t)KLD * HDIM) / 8192, 256>>>((uint4*)pwv, (const float4*)Wv);
    cvt_half4<<<((size_t)HDIM * QLD) / 8192, 256>>>((uint4*)pwo, (const float4*)Wo);

    k_proj_qkv<<<dim3(48, ROWS / 128), 128, PSMEM_H>>>();
    rope_q<<<ROWS, 256>>>(cosT, sinT);
    rope_k<<<ROWS, 256>>>(cosT, sinT);
    k_flash<<<dim3(SEQ / 128, NBH), 256, FSMEM>>>();
    k_out_proj<<<dim3(HDIM / 128, ROWS / 128), 128, PSMEM_H>>>(out);
}

// round 11
// speedup vs baseline: 2.5058x; 1.0597x over previous
#include <cuda_runtime.h>
#include <cuda_fp16.h>
#include <cstdint>

#define SEQ 2048
#define NB 2
#define ROWS (NB * SEQ)      // 4096 total (b,s) rows
#define HDIM 4096
#define NH 32
#define NKV 8
#define HD 128
#define QLD (NH * HD)        // 4096
#define KLD (NKV * HD)       // 1024
#define NBH (NB * NH)        // 64

// ---------------- scratch (static device allocations; no cudaMalloc) -------
__device__ __half g_hs16[(size_t)ROWS * HDIM];
__device__ __half g_wq16[(size_t)QLD * HDIM];
__device__ __half g_wk16[(size_t)KLD * HDIM];
__device__ __half g_wv16[(size_t)KLD * HDIM];
__device__ __half g_wo16[(size_t)HDIM * QLD];
__device__ __half g_q16[(size_t)ROWS * QLD];              // roped Q (scaled)
__device__ __half g_k16[(size_t)ROWS * KLD];              // roped K
__device__ __half g_v16t[(size_t)NB * KLD * SEQ];         // V transposed [b][kv][d][s]
__device__ __half g_attn16[(size_t)ROWS * QLD];           // flash out

// ---------------- helpers ---------------------------------------------------
__device__ __forceinline__ uint32_t smem_u32(const void* p) {
    uint32_t a;
    asm("{ .reg .u64 t; cvta.to.shared.u64 t, %1; cvt.u32.u64 %0, t; }" : "=r"(a) : "l"(p));
    return a;
}
__device__ __forceinline__ uint32_t packh2(float a, float b) {
    __half2 h = __floats2half2_rn(a, b);
    return *(uint32_t*)&h;
}

#define CP_ASYNC16(dst, src) \
    asm volatile("cp.async.cg.shared.global [%0], [%1], 16;" :: "r"(dst), "l"(src) : "memory")
#define CP_COMMIT() asm volatile("cp.async.commit_group;" ::: "memory")
#define CP_WAIT(n)  asm volatile("cp.async.wait_group %0;" :: "n"(n) : "memory")

#define LDSM4(r0, r1, r2, r3, addr) \
    asm volatile("ldmatrix.sync.aligned.m8n8.x4.shared.b16 {%0,%1,%2,%3}, [%4];" \
        : "=r"(r0), "=r"(r1), "=r"(r2), "=r"(r3) : "r"(addr))

// fp16 mma: 16x8x16, fp32 accumulate
__device__ __forceinline__ void mma16(float* c, const uint32_t* a, const uint32_t* b) {
    asm volatile(
        "mma.sync.aligned.m16n8k16.row.col.f32.f16.f16.f32 "
        "{%0,%1,%2,%3}, {%4,%5,%6,%7}, {%8,%9}, {%0,%1,%2,%3};\n"
        : "+f"(c[0]), "+f"(c[1]), "+f"(c[2]), "+f"(c[3])
        : "r"(a[0]), "r"(a[1]), "r"(a[2]), "r"(a[3]), "r"(b[0]), "r"(b[1]));
}

// ============================================================================
// Projection GEMM (fp16 operands): C[128,128] tile = A * B^T.
// A [M,K], B [N,K] row-major __half.  128 threads = 4 warps (2m x 2n),
// warp tile 64x64.  BK=64, 3-stage cp.async, 2 CTAs/SM, ldmatrix fragments.
// MODE 0: fp32 C out (out_proj).
// MODE 1: V transposed fp16 out -> g_v16t.
// MODE 2: RoPE + scale + fp16 out -> g_q16 (tile cols = one head).
// MODE 3: RoPE + fp16 out -> g_k16.
// ============================================================================
#define HBK 64
#define HSTAGE 3
#define HSTR 72                                // halves (64 + 8 pad)
#define HT_BYTES (128 * HSTR * 2)              // 18432 per tile
#define HSTAGE_BYTES (2 * HT_BYTES)            // 36864
#define PSMEM_H (HSTAGE * HSTAGE_BYTES)        // 110592

template <int MODE>
__device__ __forceinline__ void pgemm_h(
    const __half* __restrict__ A, const __half* __restrict__ B, float* __restrict__ C,
    int m0, int n0, int K, int lda, int ldb, int ldc,
    const float* __restrict__ cosT, const float* __restrict__ sinT)
{
    extern __shared__ float dsm[];
    const uint32_t sbase = smem_u32(dsm);

    const int tid = threadIdx.x;
    const int arow = tid >> 3;          // 0..15 (rows arow + 16*i)
    const int ac = (tid & 7) << 3;      // 0,8,...,56 halves

    const int warp = tid >> 5;
    const int lane = tid & 31;
    const int wm = (warp & 1) << 6;     // 0,64
    const int wn = (warp >> 1) << 6;    // 0,64
    const int g  = lane >> 2;
    const int tg = lane & 3;

    const int lrA = (((lane >> 3) & 1) << 3) + (lane & 7);
    const int lkA = (lane >> 4) << 3;
    const int lrB = (((lane >> 4) & 1) << 3) + (lane & 7);
    const int lkB = ((lane >> 3) & 1) << 3;

    uint32_t offA[4], offB[4];
#pragma unroll
    for (int mt = 0; mt < 4; mt++)
        offA[mt] = (uint32_t)(((wm + mt * 16 + lrA) * HSTR + lkA) * 2);
#pragma unroll
    for (int np = 0; np < 4; np++)
        offB[np] = (uint32_t)(((wn + np * 16 + lrB) * HSTR + lkB) * 2) + HT_BYTES;

    float acc[4][8][4];
#pragma unroll
    for (int i = 0; i < 4; i++)
#pragma unroll
        for (int j = 0; j < 8; j++)
#pragma unroll
            for (int l = 0; l < 4; l++) acc[i][j][l] = 0.f;

    const int nk = K / HBK;

#define HLOAD(s) do {                                                              \
        const uint32_t sa_u = sbase + (uint32_t)((s) % HSTAGE) * HSTAGE_BYTES;     \
        const uint32_t sb_u = sa_u + HT_BYTES;                                     \
        const __half* pa_ = A + (size_t)(m0 + arow) * lda + (s) * HBK + ac;        \
        const __half* pb_ = B + (size_t)(n0 + arow) * ldb + (s) * HBK + ac;        \
        _Pragma("unroll")                                                          \
        for (int r_ = 0; r_ < 128; r_ += 16) {                                     \
            CP_ASYNC16(sa_u + (uint32_t)((arow + r_) * HSTR + ac) * 2u,            \
                       pa_ + (size_t)r_ * lda);                                    \
            CP_ASYNC16(sb_u + (uint32_t)((arow + r_) * HSTR + ac) * 2u,            \
                       pb_ + (size_t)r_ * ldb);                                    \
        }                                                                          \
    } while (0)

#pragma unroll
    for (int s = 0; s < HSTAGE - 1; s++) {
        if (s < nk) HLOAD(s);
        CP_COMMIT();
    }

    for (int kt = 0; kt < nk; kt++) {
        CP_WAIT(HSTAGE - 2);
        __syncthreads();
        if (kt + HSTAGE - 1 < nk) HLOAD(kt + HSTAGE - 1);
        CP_COMMIT();

        const uint32_t st_u = sbase + (uint32_t)((kt % HSTAGE) * HSTAGE_BYTES);

#pragma unroll
        for (int ks = 0; ks < 4; ks++) {       // four k16 steps per 64-k tile
            const uint32_t kadd = ks * 32;     // +16 halves
            uint32_t af[4][4];
#pragma unroll
            for (int mt = 0; mt < 4; mt++)
                LDSM4(af[mt][0], af[mt][1], af[mt][2], af[mt][3],
                      st_u + offA[mt] + kadd);
            uint32_t bf[8][2];
#pragma unroll
            for (int np = 0; np < 4; np++)
                LDSM4(bf[2 * np][0], bf[2 * np][1], bf[2 * np + 1][0], bf[2 * np + 1][1],
                      st_u + offB[np] + kadd);
#pragma unroll
            for (int mt = 0; mt < 4; mt++)
#pragma unroll
                for (int nt = 0; nt < 8; nt++)
                    mma16(acc[mt][nt], af[mt], bf[nt]);
        }
        __syncthreads();
    }

    if (MODE == 0 || MODE == 1) {
#pragma unroll
        for (int mt = 0; mt < 4; mt++) {
            const int r = m0 + wm + mt * 16 + g;
#pragma unroll
            for (int nt = 0; nt < 8; nt++) {
                const int c = n0 + wn + nt * 8 + (tg << 1);
                const float v0 = acc[mt][nt][0], v1 = acc[mt][nt][1];
                const float v2 = acc[mt][nt][2], v3 = acc[mt][nt][3];
                if (MODE == 0) {
                    float* p0 = C + (size_t)r * ldc + c;
                    *(float2*)p0 = make_float2(v0, v1);
                    float* p1 = p0 + (size_t)8 * ldc;
                    *(float2*)p1 = make_float2(v2, v3);
                } else {
                    const int b = r >> 11, s = r & (SEQ - 1);
                    const size_t base = ((size_t)b * KLD + c) * SEQ + s;
                    g_v16t[base]           = __float2half_rn(v0);
                    g_v16t[base + SEQ]     = __float2half_rn(v1);
                    g_v16t[base + 8]       = __float2half_rn(v2);
                    g_v16t[base + SEQ + 8] = __float2half_rn(v3);
                }
            }
        }
    } else {
        // ---- RoPE epilogue: stage fp32 tile in smem, mix (d, d+64), emit fp16
        float* sm = dsm;   // 128 x 132 fp32 tile (67.6 KB <= PSMEM_H)
#pragma unroll
        for (int mt = 0; mt < 4; mt++) {
            const int r = wm + mt * 16 + g;
#pragma unroll
            for (int nt = 0; nt < 8; nt++) {
                const int c = wn + nt * 8 + (tg << 1);
                *(float2*)&sm[r * 132 + c]       = make_float2(acc[mt][nt][0], acc[mt][nt][1]);
                *(float2*)&sm[(r + 8) * 132 + c] = make_float2(acc[mt][nt][2], acc[mt][nt][3]);
            }
        }
        __syncthreads();

        const float scq = (MODE == 2) ? 0.08838834764831845f : 1.0f;
        __half* outb = (MODE == 2) ? g_q16 : g_k16;
        const int ldo = (MODE == 2) ? QLD : KLD;

#pragma unroll
        for (int i = 0; i < 32; i++) {
            const int idx = tid + i * 128;       // 0..4095
            const int row = idx >> 5;            // 0..127
            const int dd = (idx & 31) << 1;      // 0,2,...,62
            const int rg = m0 + row;
            const int s = rg & (SEQ - 1);
            const float2 x1 = *(const float2*)&sm[row * 132 + dd];
            const float2 x2 = *(const float2*)&sm[row * 132 + dd + 64];
            const float2 c1 = *(const float2*)&cosT[(size_t)s * HD + dd];
            const float2 s1 = *(const float2*)&sinT[(size_t)s * HD + dd];
            const float2 c2 = *(const float2*)&cosT[(size_t)s * HD + dd + 64];
            const float2 s2 = *(const float2*)&sinT[(size_t)s * HD + dd + 64];
            __half* ob = outb + (size_t)rg * ldo + n0 + dd;
            *(__half2*)ob = __floats2half2_rn((x1.x * c1.x - x2.x * s1.x) * scq,
                                              (x1.y * c1.y - x2.y * s1.y) * scq);
            *(__half2*)(ob + 64) = __floats2half2_rn((x2.x * c2.x + x1.x * s2.x) * scq,
                                                     (x2.y * c2.y + x1.y * s2.y) * scq);
        }
    }
#undef HLOAD
}

// ---------------- projection wrappers ----------------------------------------
// merged QKV: grid (48, 32); x: [0,32)->Q(rope), [32,40)->K(rope), [40,48)->V(transpose)
__global__ void __launch_bounds__(128, 2) k_proj_qkv(const float* __restrict__ cosT,
                                                     const float* __restrict__ sinT) {
    const int nb = blockIdx.x;
    const int m0 = blockIdx.y * 128;
    if (nb < 32) {
        pgemm_h<2>(g_hs16, g_wq16, nullptr, m0, nb * 128, HDIM, HDIM, HDIM, 0, cosT, sinT);
    } else if (nb < 40) {
        pgemm_h<3>(g_hs16, g_wk16, nullptr, m0, (nb - 32) * 128, HDIM, HDIM, HDIM, 0, cosT, sinT);
    } else {
        pgemm_h<1>(g_hs16, g_wv16, nullptr, m0, (nb - 40) * 128, HDIM, HDIM, HDIM, 0, nullptr, nullptr);
    }
}
__global__ void __launch_bounds__(128, 2) k_out_proj(float* __restrict__ out) {
    pgemm_h<0>(g_attn16, g_wo16, out, blockIdx.y * 128, blockIdx.x * 128,
               QLD, QLD, HDIM, HDIM, nullptr, nullptr);
}

// ============================================================================
// Fused flash attention (causal, online softmax), fp16 mma, ldmatrix frags.
// Grid (16 q-blocks [reversed], 64 z).  256 threads = 8 warps, 16 Q rows each.
// Q pre-scaled by 1/sqrt(HD).  V read transposed from g_v16t.
// ============================================================================
#define KSTRW 68                    // K/Q smem row stride words (136 halves, 272B)
#define VSTRW 36                    // V^T row stride words (72 halves, 144B)
#define K_TILE_W (64 * KSTRW)       // 4352 words
#define V_TILE_W (128 * VSTRW)      // 4608 words
#define FSMEM ((2 * K_TILE_W + 2 * V_TILE_W) * 4)   // 71680 bytes

__global__ void __launch_bounds__(256, 1) k_flash() {
    extern __shared__ uint32_t fsm[];
    const uint32_t sbase = smem_u32(fsm);

    const int tid = threadIdx.x;
    const int wid = tid >> 5, lane = tid & 31;
    const int g = lane >> 2, tg = lane & 3;
    const int wm = wid * 16;

    const int z = blockIdx.y, b = z >> 5, h = z & 31, kvh = h >> 2;
    const int qb = (int)(gridDim.x - 1 - blockIdx.x);
    const int q0 = qb * 128;
    const int nkv = 2 * qb + 2;

    const __half* Qp = g_q16 + (size_t)(b * SEQ + q0) * QLD + h * HD;
    const __half* Kp = g_k16 + (size_t)b * SEQ * KLD + kvh * HD;
    const __half* Vt = g_v16t + (size_t)(b * NKV + kvh) * HD * SEQ;

    const int lrB = (((lane >> 4) & 1) << 3) + (lane & 7);
    const int lkB = ((lane >> 3) & 1) << 3;
    const int lrA = (((lane >> 3) & 1) << 3) + (lane & 7);
    const int lkA = (lane >> 4) << 3;

    // ---- stage Q tile (128 rows x 128 halves, 272B row stride)
#pragma unroll
    for (int i = 0; i < 8; i++) {
        const int op = tid + i * 256;
        const int row = op >> 4, ch = op & 15;
        CP_ASYNC16(sbase + (uint32_t)(row * 272 + ch * 16), Qp + (size_t)row * QLD + ch * 8);
    }
    CP_COMMIT();
    CP_WAIT(0);
    __syncthreads();

    uint32_t qf[8][4];
    {
        const uint32_t qoff = sbase + (uint32_t)((wm + lrA) * 272 + lkA * 2);
#pragma unroll
        for (int ks = 0; ks < 8; ks++)
            LDSM4(qf[ks][0], qf[ks][1], qf[ks][2], qf[ks][3], qoff + ks * 32);
    }
    __syncthreads();

    const uint32_t kbu[2] = { sbase, sbase + K_TILE_W * 4u };
    const uint32_t vbu[2] = { sbase + 2u * K_TILE_W * 4u,
                              sbase + 2u * K_TILE_W * 4u + V_TILE_W * 4u };

    uint32_t offK[4], offV[8];
#pragma unroll
    for (int np = 0; np < 4; np++)
        offK[np] = (uint32_t)((np * 16 + lrB) * 272 + lkB * 2);
#pragma unroll
    for (int np = 0; np < 8; np++)
        offV[np] = (uint32_t)((np * 16 + lrB) * 144 + lkB * 2);

#define LOAD_KV(t) do {                                                          \
        const int kv0_ = (t) * 64, p_ = (t) & 1;                                 \
        _Pragma("unroll")                                                        \
        for (int i_ = 0; i_ < 4; i_++) {                                         \
            const int op_ = tid + i_ * 256;                                      \
            const int krow_ = op_ >> 4, kch_ = op_ & 15;                         \
            CP_ASYNC16(kbu[p_] + (uint32_t)(krow_ * 272 + kch_ * 16),            \
                       Kp + (size_t)(kv0_ + krow_) * KLD + kch_ * 8);            \
            const int vrow_ = op_ >> 3, vch_ = op_ & 7;                          \
            CP_ASYNC16(vbu[p_] + (uint32_t)(vrow_ * 144 + vch_ * 16),            \
                       Vt + (size_t)vrow_ * SEQ + kv0_ + vch_ * 8);              \
        }                                                                        \
        CP_COMMIT();                                                             \
    } while (0)

    LOAD_KV(0);
    LOAD_KV(1);

    float mrow0 = -1e30f, mrow1 = -1e30f;
    float lrow0 = 0.f, lrow1 = 0.f;
    float o[16][4];
#pragma unroll
    for (int i = 0; i < 16; i++)
#pragma unroll
        for (int j = 0; j < 4; j++) o[i][j] = 0.f;

    const int r0g = q0 + wm + g, r1g = r0g + 8;

    for (int t = 0; t < nkv; t++) {
        const int p = t & 1, kv0 = t * 64;
        if (t + 1 < nkv) { CP_WAIT(1); } else { CP_WAIT(0); }
        __syncthreads();

        float sacc[8][4];
#pragma unroll
        for (int nt = 0; nt < 8; nt++)
#pragma unroll
            for (int j = 0; j < 4; j++) sacc[nt][j] = 0.f;

#pragma unroll
        for (int ks = 0; ks < 8; ks++) {
            uint32_t bf[8][2];
#pragma unroll
            for (int np = 0; np < 4; np++)
                LDSM4(bf[2 * np][0], bf[2 * np][1], bf[2 * np + 1][0], bf[2 * np + 1][1],
                      kbu[p] + offK[np] + ks * 32);
#pragma unroll
            for (int nt = 0; nt < 8; nt++)
                mma16(sacc[nt], qf[ks], bf[nt]);
        }

        float mnew0 = mrow0, mnew1 = mrow1;
        const bool domask = (kv0 + 63 > q0);
#pragma unroll
        for (int nt = 0; nt < 8; nt++) {
            const int c0 = kv0 + nt * 8 + 2 * tg, c1 = c0 + 1;
            float v0 = sacc[nt][0], v1 = sacc[nt][1];
            float v2 = sacc[nt][2], v3 = sacc[nt][3];
            if (domask) {
                if (c0 > r0g) v0 = -1e30f;
                if (c1 > r0g) v1 = -1e30f;
                if (c0 > r1g) v2 = -1e30f;
                if (c1 > r1g) v3 = -1e30f;
            }
            sacc[nt][0] = v0; sacc[nt][1] = v1; sacc[nt][2] = v2; sacc[nt][3] = v3;
            mnew0 = fmaxf(mnew0, fmaxf(v0, v1));
            mnew1 = fmaxf(mnew1, fmaxf(v2, v3));
        }
        mnew0 = fmaxf(mnew0, __shfl_xor_sync(0xffffffffu, mnew0, 1));
        mnew0 = fmaxf(mnew0, __shfl_xor_sync(0xffffffffu, mnew0, 2));
        mnew1 = fmaxf(mnew1, __shfl_xor_sync(0xffffffffu, mnew1, 1));
        mnew1 = fmaxf(mnew1, __shfl_xor_sync(0xffffffffu, mnew1, 2));

        const float f0 = __expf(mrow0 - mnew0);
        const float f1 = __expf(mrow1 - mnew1);

        float rs0 = 0.f, rs1 = 0.f;
#pragma unroll
        for (int nt = 0; nt < 8; nt++) {
            const float e0 = __expf(sacc[nt][0] - mnew0);
            const float e1 = __expf(sacc[nt][1] - mnew0);
            const float e2 = __expf(sacc[nt][2] - mnew1);
            const float e3 = __expf(sacc[nt][3] - mnew1);
            sacc[nt][0] = e0; sacc[nt][1] = e1; sacc[nt][2] = e2; sacc[nt][3] = e3;
            rs0 += e0 + e1;
            rs1 += e2 + e3;
        }
        rs0 += __shfl_xor_sync(0xffffffffu, rs0, 1);
        rs0 += __shfl_xor_sync(0xffffffffu, rs0, 2);
        rs1 += __shfl_xor_sync(0xffffffffu, rs1, 1);
        rs1 += __shfl_xor_sync(0xffffffffu, rs1, 2);

        lrow0 = lrow0 * f0 + rs0;
        lrow1 = lrow1 * f1 + rs1;
        mrow0 = mnew0;
        mrow1 = mnew1;

#pragma unroll
        for (int nt2 = 0; nt2 < 16; nt2++) {
            o[nt2][0] *= f0; o[nt2][1] *= f0;
            o[nt2][2] *= f1; o[nt2][3] *= f1;
        }

#pragma unroll
        for (int ks2 = 0; ks2 < 4; ks2++) {
            uint32_t pa[4];
            pa[0] = packh2(sacc[2 * ks2][0],     sacc[2 * ks2][1]);
            pa[1] = packh2(sacc[2 * ks2][2],     sacc[2 * ks2][3]);
            pa[2] = packh2(sacc[2 * ks2 + 1][0], sacc[2 * ks2 + 1][1]);
            pa[3] = packh2(sacc[2 * ks2 + 1][2], sacc[2 * ks2 + 1][3]);
            uint32_t vf[16][2];
#pragma unroll
            for (int np = 0; np < 8; np++)
                LDSM4(vf[2 * np][0], vf[2 * np][1], vf[2 * np + 1][0], vf[2 * np + 1][1],
                      vbu[p] + offV[np] + ks2 * 32);
#pragma unroll
            for (int nt2 = 0; nt2 < 16; nt2++)
                mma16(o[nt2], pa, vf[nt2]);
        }

        __syncthreads();
        if (t + 2 < nkv) LOAD_KV(t + 2);
    }

    const float inv0 = 1.f / lrow0;
    const float inv1 = 1.f / lrow1;
    __half* orow0 = g_attn16 + (size_t)(b * SEQ + r0g) * QLD + h * HD;
    __half* orow1 = g_attn16 + (size_t)(b * SEQ + r1g) * QLD + h * HD;
#pragma unroll
    for (int nt2 = 0; nt2 < 16; nt2++) {
        const int c = nt2 * 8 + 2 * tg;
        *(__half2*)(orow0 + c) = __floats2half2_rn(o[nt2][0] * inv0, o[nt2][1] * inv0);
        *(__half2*)(orow1 + c) = __floats2half2_rn(o[nt2][2] * inv1, o[nt2][3] * inv1);
    }
#undef LOAD_KV
}

// ---------------- fp32 -> fp16 prepass (MLP=4) --------------------------------
__global__ void cvt_half4(uint4* __restrict__ dst, const float4* __restrict__ src) {
    const size_t base = (size_t)blockIdx.x * 1024 + threadIdx.x;
#pragma unroll
    for (int i = 0; i < 4; i++) {
        const size_t oi = base + i * 256;
        const float4 a = src[2 * oi];
        const float4 b = src[2 * oi + 1];
        __half2 h0 = __floats2half2_rn(a.x, a.y);
        __half2 h1 = __floats2half2_rn(a.z, a.w);
        __half2 h2 = __floats2half2_rn(b.x, b.y);
        __half2 h3 = __floats2half2_rn(b.z, b.w);
        uint4 o4;
        o4.x = *(uint32_t*)&h0;
        o4.y = *(uint32_t*)&h1;
        o4.z = *(uint32_t*)&h2;
        o4.w = *(uint32_t*)&h3;
        dst[oi] = o4;
    }
}

// ---------------- launch -----------------------------------------------------
extern "C" void kernel_launch(void* const* d_in, const int* in_sizes, int n_in,
                              void* d_out, int out_size) {
    (void)in_sizes; (void)n_in; (void)out_size;
    const float* hs   = (const float*)d_in[0];
    const float* Wq   = (const float*)d_in[1];
    const float* Wk   = (const float*)d_in[2];
    const float* Wv   = (const float*)d_in[3];
    const float* Wo   = (const float*)d_in[4];
    const float* cosT = (const float*)d_in[5];
    const float* sinT = (const float*)d_in[6];
    float* out = (float*)d_out;

    static bool attr_set = false;
    if (!attr_set) {
        cudaFuncSetAttribute(k_proj_qkv, cudaFuncAttributeMaxDynamicSharedMemorySize, PSMEM_H);
        cudaFuncSetAttribute(k_out_proj, cudaFuncAttributeMaxDynamicSharedMemorySize, PSMEM_H);
        cudaFuncSetAttribute(k_flash,    cudaFuncAttributeMaxDynamicSharedMemorySize, FSMEM);
        attr_set = true;
    }

    void* phs;  cudaGetSymbolAddress(&phs, g_hs16);
    void* pwq;  cudaGetSymbolAddress(&pwq, g_wq16);
    void* pwk;  cudaGetSymbolAddress(&pwk, g_wk16);
    void* pwv;  cudaGetSymbolAddress(&pwv, g_wv16);
    void* pwo;  cudaGetSymbolAddress(&pwo, g_wo16);

    cvt_half4<<<((size_t)ROWS * HDIM) / 8192, 256>>>((uint4*)phs, (const float4*)hs);
    cvt_half4<<<((size_t)QLD * HDIM) / 8192, 256>>>((uint4*)pwq, (const float4*)Wq);
    cvt_half4<<<((size_t)KLD * HDIM) / 8192, 256>>>((uint4*)pwk, (const float4*)Wk);
    cvt_half4<<<((size_t)KLD * HDIM) / 8192, 256>>>((uint4*)pwv, (const float4*)Wv);
    cvt_half4<<<((size_t)HDIM * QLD) / 8192, 256>>>((uint4*)pwo, (const float4*)Wo);

    k_proj_qkv<<<dim3(48, ROWS / 128), 128, PSMEM_H>>>(cosT, sinT);
    k_flash<<<dim3(SEQ / 128, NBH), 256, FSMEM>>>();
    k_out_proj<<<dim3(HDIM / 128, ROWS / 128), 128, PSMEM_H>>>(out);
}